// round 14
// baseline (speedup 1.0000x reference)
#include <cuda_runtime.h>
#include <cuda_bf16.h>
#include <math.h>
#include <stdint.h>

// Problem constants
constexpr int PB = 2;      // batch
constexpr int PT = 2048;   // query seq
constexpr int PS = 2048;   // key/value seq
constexpr int PD = 1024;   // model dim
constexpr int PH = 16;     // heads
constexpr int PDK = 64;    // head dim

constexpr int GEMM_M = PB * PT;  // 4096
constexpr int GEMM_N = PD;       // 1024
constexpr int GEMM_K = PD;       // 1024

// ---------------------------------------------------------------------------
// Scratch (device globals — no allocation allowed)
// ---------------------------------------------------------------------------
__device__ __nv_bfloat16 g_qhi[(size_t)PB * PH * PT * PDK];
__device__ __nv_bfloat16 g_qlo[(size_t)PB * PH * PT * PDK];
__device__ __nv_bfloat16 g_khi[(size_t)PB * PH * PS * PDK];
__device__ __nv_bfloat16 g_klo[(size_t)PB * PH * PS * PDK];
__device__ __nv_bfloat16 g_vhi[(size_t)PB * PH * PS * PDK];
__device__ __nv_bfloat16 g_vlo[(size_t)PB * PH * PS * PDK];

__device__ __nv_bfloat16 g_pa_hi[3][(size_t)GEMM_M * GEMM_K];
__device__ __nv_bfloat16 g_pa_lo[3][(size_t)GEMM_M * GEMM_K];
__device__ __nv_bfloat16 g_pb_hi[4][(size_t)GEMM_N * GEMM_K];
__device__ __nv_bfloat16 g_pb_lo[4][(size_t)GEMM_N * GEMM_K];
__device__ __nv_bfloat16 g_ahi[(size_t)GEMM_M * GEMM_K];
__device__ __nv_bfloat16 g_alo[(size_t)GEMM_M * GEMM_K];

// ---------------------------------------------------------------------------
// PTX helpers (base ISA only)
// ---------------------------------------------------------------------------
__device__ __forceinline__ uint32_t smem_u32(const void* p) {
    uint32_t a;
    asm("{ .reg .u64 t; cvta.to.shared.u64 t, %1; cvt.u32.u64 %0, t; }"
        : "=r"(a) : "l"(p));
    return a;
}

__device__ __forceinline__ void cp16(uint32_t saddr, const void* gaddr) {
    asm volatile("cp.async.cg.shared.global [%0], [%1], 16;"
                 :: "r"(saddr), "l"(gaddr) : "memory");
}
#define CP_COMMIT() asm volatile("cp.async.commit_group;" ::: "memory")
#define CP_WAIT1()  asm volatile("cp.async.wait_group 1;" ::: "memory")
#define CP_WAIT0()  asm volatile("cp.async.wait_group 0;" ::: "memory")

__device__ __forceinline__ void ldsm_x4(uint32_t& r0, uint32_t& r1,
                                        uint32_t& r2, uint32_t& r3,
                                        uint32_t addr) {
    asm volatile("ldmatrix.sync.aligned.m8n8.x4.shared.b16 {%0,%1,%2,%3}, [%4];"
                 : "=r"(r0), "=r"(r1), "=r"(r2), "=r"(r3) : "r"(addr));
}

__device__ __forceinline__ void ldsm_x4_t(uint32_t& r0, uint32_t& r1,
                                          uint32_t& r2, uint32_t& r3,
                                          uint32_t addr) {
    asm volatile("ldmatrix.sync.aligned.m8n8.x4.trans.shared.b16 {%0,%1,%2,%3}, [%4];"
                 : "=r"(r0), "=r"(r1), "=r"(r2), "=r"(r3) : "r"(addr));
}

__device__ __forceinline__ void mma_bf16(float* d, const uint32_t* a,
                                         const uint32_t* b) {
    asm volatile(
        "mma.sync.aligned.m16n8k16.row.col.f32.bf16.bf16.f32 "
        "{%0,%1,%2,%3}, {%4,%5,%6,%7}, {%8,%9}, {%0,%1,%2,%3};"
        : "+f"(d[0]), "+f"(d[1]), "+f"(d[2]), "+f"(d[3])
        : "r"(a[0]), "r"(a[1]), "r"(a[2]), "r"(a[3]),
          "r"(b[0]), "r"(b[1]));
}

// split (a, b) fp32 pair into packed bf16x2 hi + bf16x2 lo
__device__ __forceinline__ void split2(float a, float b,
                                       uint32_t& hi, uint32_t& lo) {
    __nv_bfloat16 ha = __float2bfloat16(a);
    __nv_bfloat16 hb = __float2bfloat16(b);
    hi = ((uint32_t)__bfloat16_as_ushort(hb) << 16) |
         (uint32_t)__bfloat16_as_ushort(ha);
    __nv_bfloat162 r = __floats2bfloat162_rn(a - __bfloat162float(ha),
                                             b - __bfloat162float(hb));
    lo = *reinterpret_cast<uint32_t*>(&r);
}

// ---------------------------------------------------------------------------
// Split kernels (fused over z planes)
// ---------------------------------------------------------------------------
struct SplitAParams {
    const float* x[3];
    __nv_bfloat16* hi[3];
    __nv_bfloat16* lo[3];
};

__global__ __launch_bounds__(256) void split_a3_kernel(SplitAParams P)
{
    const int z = blockIdx.z;
    const float4* xp = (const float4*)P.x[z];
    uint32_t* hp = (uint32_t*)P.hi[z];
    uint32_t* lp = (uint32_t*)P.lo[z];
    const int base = blockIdx.x * 1024 + threadIdx.x;

    float4 v[4];
#pragma unroll
    for (int j = 0; j < 4; j++) v[j] = xp[base + j * 256];

#pragma unroll
    for (int j = 0; j < 4; j++) {
        int i = base + j * 256;
        uint32_t h0, l0, h1, l1;
        split2(v[j].x, v[j].y, h0, l0);
        split2(v[j].z, v[j].w, h1, l1);
        hp[2 * i + 0] = h0;
        hp[2 * i + 1] = h1;
        lp[2 * i + 0] = l0;
        lp[2 * i + 1] = l1;
    }
}

struct SplitWParams {
    const float* w[4];
    __nv_bfloat16* hi[4];
    __nv_bfloat16* lo[4];
};

__global__ __launch_bounds__(256) void split_w4_kernel(SplitWParams P)
{
    __shared__ float t[32][33];
    int z = blockIdx.z;
    const float* W = P.w[z];
    __nv_bfloat16* hi = P.hi[z];
    __nv_bfloat16* lo = P.lo[z];
    int n0 = blockIdx.x * 32, k0 = blockIdx.y * 32;
    int tx = threadIdx.x, ty = threadIdx.y;
#pragma unroll
    for (int i = 0; i < 32; i += 8)
        t[ty + i][tx] = W[(size_t)(k0 + ty + i) * GEMM_N + n0 + tx];
    __syncthreads();
#pragma unroll
    for (int i = 0; i < 32; i += 8) {
        float v = t[tx][ty + i];
        __nv_bfloat16 h = __float2bfloat16(v);
        size_t o = (size_t)(n0 + ty + i) * GEMM_K + k0 + tx;
        hi[o] = h;
        lo[o] = __float2bfloat16(v - __bfloat162float(h));
    }
}

// ---------------------------------------------------------------------------
// HMMA GEMM core (measured-good Round 12/13): 128x128 block, BK=32, 8 warps,
// hi/lo 3-pass, 2-stage, 80KB smem -> 2 CTAs/SM, B in 4-column halves.
// ---------------------------------------------------------------------------
constexpr int GBK = 32;
constexpr int GSTR = 40;
constexpr int GTILE_B = 128 * GSTR * 2;         // 10240
constexpr int GSTAGE_B = 4 * GTILE_B;           // 40960
constexpr int GSM_TOTAL = 2 * GSTAGE_B;         // 81920
constexpr int GNCH = GEMM_K / GBK;              // 32

__device__ __forceinline__ void g_load_tile(
    uint32_t sdst, const __nv_bfloat16* __restrict__ g, int row0, int k0, int tid)
{
#pragma unroll
    for (int i = 0; i < 2; i++) {
        int s = tid + i * 256;
        int r = s >> 2;
        int c = s & 3;
        cp16(sdst + (uint32_t)(r * (GSTR * 2) + c * 16),
             g + (size_t)(row0 + r) * GEMM_K + k0 + c * 8);
    }
}

__device__ __forceinline__ void g_load_stage(
    uint32_t st, const __nv_bfloat16* Ahi, const __nv_bfloat16* Alo,
    const __nv_bfloat16* Bhi, const __nv_bfloat16* Blo,
    int bm, int bn, int k0, int tid)
{
    g_load_tile(st + 0 * GTILE_B, Ahi, bm, k0, tid);
    g_load_tile(st + 1 * GTILE_B, Alo, bm, k0, tid);
    g_load_tile(st + 2 * GTILE_B, Bhi, bn, k0, tid);
    g_load_tile(st + 3 * GTILE_B, Blo, bn, k0, tid);
    CP_COMMIT();
}

__device__ __forceinline__ void gemm_core(
    uint32_t sb, int tid,
    const __nv_bfloat16* __restrict__ Ahi, const __nv_bfloat16* __restrict__ Alo,
    const __nv_bfloat16* __restrict__ Bhi, const __nv_bfloat16* __restrict__ Blo,
    int bm, int bn, float acc[2][8][4])
{
    const int lane = tid & 31;
    const int wid = tid >> 5;
    const int wm = wid >> 1;
    const int wn = wid & 1;

    const int a_r = ((lane >> 3) & 1) * 8 + (lane & 7);
    const int a_c = (lane >> 4) * 8;
    const int b_r = (lane >> 4) * 8 + (lane & 7);
    const int b_c = ((lane >> 3) & 1) * 8;

    g_load_stage(sb, Ahi, Alo, Bhi, Blo, bm, bn, 0, tid);

    for (int c = 0; c < GNCH; c++) {
        if (c + 1 < GNCH) {
            g_load_stage(sb + ((c + 1) & 1) * GSTAGE_B, Ahi, Alo, Bhi, Blo,
                         bm, bn, (c + 1) * GBK, tid);
            CP_WAIT1();
        } else {
            CP_WAIT0();
        }
        __syncthreads();

        const uint32_t st = sb + (c & 1) * GSTAGE_B;
        const uint32_t sAhi = st + 0 * GTILE_B;
        const uint32_t sAlo = st + 1 * GTILE_B;
        const uint32_t sBhi = st + 2 * GTILE_B;
        const uint32_t sBlo = st + 3 * GTILE_B;

#pragma unroll
        for (int ks = 0; ks < 2; ks++) {
            const int kc = ks * 16;
            uint32_t ah[2][4], al[2][4];
#pragma unroll
            for (int ma = 0; ma < 2; ma++) {
                uint32_t off =
                    (uint32_t)((wm * 32 + ma * 16 + a_r) * (GSTR * 2) +
                               (kc + a_c) * 2);
                ldsm_x4(ah[ma][0], ah[ma][1], ah[ma][2], ah[ma][3], sAhi + off);
                ldsm_x4(al[ma][0], al[ma][1], al[ma][2], al[ma][3], sAlo + off);
            }
#pragma unroll
            for (int h2 = 0; h2 < 2; h2++) {
                uint32_t bh[4][2], bl[4][2];
#pragma unroll
                for (int pa = 0; pa < 2; pa++) {
                    uint32_t off =
                        (uint32_t)((wn * 64 + (h2 * 2 + pa) * 16 + b_r) *
                                       (GSTR * 2) +
                                   (kc + b_c) * 2);
                    ldsm_x4(bh[2 * pa][0], bh[2 * pa][1],
                            bh[2 * pa + 1][0], bh[2 * pa + 1][1], sBhi + off);
                    ldsm_x4(bl[2 * pa][0], bl[2 * pa][1],
                            bl[2 * pa + 1][0], bl[2 * pa + 1][1], sBlo + off);
                }
#pragma unroll
                for (int ma = 0; ma < 2; ma++)
#pragma unroll
                    for (int nb = 0; nb < 4; nb++) {
                        int na = h2 * 4 + nb;
                        mma_bf16(acc[ma][na], ah[ma], bh[nb]);
                        mma_bf16(acc[ma][na], ah[ma], bl[nb]);
                        mma_bf16(acc[ma][na], al[ma], bh[nb]);
                    }
            }
        }
        __syncthreads();
    }
}

struct ProjParams {
    const __nv_bfloat16* ah[3];
    const __nv_bfloat16* al[3];
    const __nv_bfloat16* bh[3];
    const __nv_bfloat16* bl[3];
    const float* bias[3];
    __nv_bfloat16* ch[3];
    __nv_bfloat16* cl[3];
    float scale[3];
};

__global__ __launch_bounds__(256, 2) void proj_gemm3_kernel(ProjParams P)
{
    extern __shared__ __align__(128) char smem[];
    const uint32_t sb = smem_u32(smem);
    const int tid = threadIdx.x;
    const int z = blockIdx.z;
    const int bm = blockIdx.y * 128;
    const int bn = blockIdx.x * 128;

    float acc[2][8][4];
#pragma unroll
    for (int i = 0; i < 2; i++)
#pragma unroll
        for (int j = 0; j < 8; j++)
#pragma unroll
            for (int r = 0; r < 4; r++) acc[i][j][r] = 0.f;

    gemm_core(sb, tid, P.ah[z], P.al[z], P.bh[z], P.bl[z], bm, bn, acc);

    const float* bias = P.bias[z];
    const float scl = P.scale[z];
    __nv_bfloat16* Chi = P.ch[z];
    __nv_bfloat16* Clo = P.cl[z];
    const int wid = tid >> 5;
    const int lane = tid & 31;
    const int wm = wid >> 1;
    const int wn = wid & 1;
    const int lr = lane >> 2;
    const int lc = (lane & 3) * 2;
#pragma unroll
    for (int ma = 0; ma < 2; ma++) {
#pragma unroll
        for (int half = 0; half < 2; half++) {
            int row = bm + wm * 32 + ma * 16 + half * 8 + lr;
            int b = row / PT;
            int t = row - b * PT;
#pragma unroll
            for (int na = 0; na < 8; na++) {
                int col = bn + wn * 64 + na * 8 + lc;
                float v0 = (acc[ma][na][half * 2 + 0] + bias[col + 0]) * scl;
                float v1 = (acc[ma][na][half * 2 + 1] + bias[col + 1]) * scl;
                int h = col >> 6;
                int dk = col & 63;
                size_t o = (((size_t)(b * PH + h) * PT) + t) * PDK + dk;
                uint32_t hp, lp;
                split2(v0, v1, hp, lp);
                *(uint32_t*)(Chi + o) = hp;
                *(uint32_t*)(Clo + o) = lp;
            }
        }
    }
}

__global__ __launch_bounds__(256, 2) void out_gemm_kernel(
    const __nv_bfloat16* __restrict__ Ahi, const __nv_bfloat16* __restrict__ Alo,
    const __nv_bfloat16* __restrict__ Bhi, const __nv_bfloat16* __restrict__ Blo,
    const float* __restrict__ bias, float* __restrict__ C)
{
    extern __shared__ __align__(128) char smem[];
    const uint32_t sb = smem_u32(smem);
    const int tid = threadIdx.x;
    const int bm = blockIdx.y * 128;
    const int bn = blockIdx.x * 128;

    float acc[2][8][4];
#pragma unroll
    for (int i = 0; i < 2; i++)
#pragma unroll
        for (int j = 0; j < 8; j++)
#pragma unroll
            for (int r = 0; r < 4; r++) acc[i][j][r] = 0.f;

    gemm_core(sb, tid, Ahi, Alo, Bhi, Blo, bm, bn, acc);

    const int wid = tid >> 5;
    const int lane = tid & 31;
    const int wm = wid >> 1;
    const int wn = wid & 1;
    const int lr = lane >> 2;
    const int lc = (lane & 3) * 2;
#pragma unroll
    for (int ma = 0; ma < 2; ma++) {
#pragma unroll
        for (int half = 0; half < 2; half++) {
            int row = bm + wm * 32 + ma * 16 + half * 8 + lr;
#pragma unroll
            for (int na = 0; na < 8; na++) {
                int col = bn + wn * 64 + na * 8 + lc;
                float v0 = acc[ma][na][half * 2 + 0] + bias[col + 0];
                float v1 = acc[ma][na][half * 2 + 1] + bias[col + 1];
                float2* dst = (float2*)(C + (size_t)row * GEMM_N + col);
                *dst = make_float2(v0, v1);
            }
        }
    }
}

// ---------------------------------------------------------------------------
// Flash attention, quadrant-decomposed: 256 threads / 8 warps as 4(M) x 2(N).
// Warp tile = 32 Q-rows x 32 KV-cols. Max-free base-2 softmax means partial
// O / l over KV halves combine by pure addition (one smem exchange at end).
// ---------------------------------------------------------------------------
constexpr int ASTR = 72;
constexpr int QTILE_B = 128 * ASTR * 2;
constexpr int KTILE_B = 64 * ASTR * 2;
constexpr int AT_SMEM = 2 * QTILE_B + 2 * 4 * KTILE_B;  // 110592

__device__ __forceinline__ void at_load_kv(
    uint32_t base, const __nv_bfloat16* kh, const __nv_bfloat16* kl,
    const __nv_bfloat16* vh, const __nv_bfloat16* vl,
    size_t gbase, int tid)
{
#pragma unroll
    for (int i = 0; i < 2; i++) {
        int s = tid + i * 256;        // 0..511
        int r = s >> 3;
        int c = s & 7;
        uint32_t doff = (uint32_t)(r * (ASTR * 2) + c * 16);
        size_t goff = gbase + (size_t)r * PDK + c * 8;
        cp16(base + 0 * KTILE_B + doff, kh + goff);
        cp16(base + 1 * KTILE_B + doff, kl + goff);
        cp16(base + 2 * KTILE_B + doff, vh + goff);
        cp16(base + 3 * KTILE_B + doff, vl + goff);
    }
}

__global__ __launch_bounds__(256, 2) void attn_mma_kernel(
    const __nv_bfloat16* __restrict__ qhi, const __nv_bfloat16* __restrict__ qlo,
    const __nv_bfloat16* __restrict__ khi, const __nv_bfloat16* __restrict__ klo,
    const __nv_bfloat16* __restrict__ vhi, const __nv_bfloat16* __restrict__ vlo,
    __nv_bfloat16* __restrict__ ohi, __nv_bfloat16* __restrict__ olo)
{
    extern __shared__ __align__(128) char smem[];
    const uint32_t sb = smem_u32(smem);
    const int tid = threadIdx.x;
    const int w = tid >> 5;
    const int lane = tid & 31;
    const int wm = w >> 1;          // 0..3: Q rows wm*32..+31
    const int wn = w & 1;           // 0..1: KV cols wn*32..+31
    const int t0 = blockIdx.x * 128;
    const int h = blockIdx.y;
    const int b = blockIdx.z;
    const size_t bh = (size_t)(b * PH + h);

    const int a_r = ((lane >> 3) & 1) * 8 + (lane & 7);
    const int a_c = (lane >> 4) * 8;
    const int b_r = (lane >> 4) * 8 + (lane & 7);
    const int b_c = ((lane >> 3) & 1) * 8;

    {
        const __nv_bfloat16* qhb = qhi + (bh * PT + t0) * PDK;
        const __nv_bfloat16* qlb = qlo + (bh * PT + t0) * PDK;
#pragma unroll
        for (int i = 0; i < 4; i++) {
            int s = tid + i * 256;    // 0..1023
            int r = s >> 3;
            int c = s & 7;
            uint32_t doff = (uint32_t)(r * (ASTR * 2) + c * 16);
            cp16(sb + doff, qhb + (size_t)r * PDK + c * 8);
            cp16(sb + QTILE_B + doff, qlb + (size_t)r * PDK + c * 8);
        }
        at_load_kv(sb + 2 * QTILE_B, khi, klo, vhi, vlo, bh * PS * PDK, tid);
        CP_COMMIT();
    }

    // lane-partial over this warp's KV half; combined additively at end
    float l[2][2];
    float oa[2][8][4];               // full DK width, partial over KV half
#pragma unroll
    for (int i = 0; i < 2; i++)
#pragma unroll
        for (int j = 0; j < 2; j++) l[i][j] = 0.f;
#pragma unroll
    for (int i = 0; i < 2; i++)
#pragma unroll
        for (int j = 0; j < 8; j++)
#pragma unroll
            for (int r = 0; r < 4; r++) oa[i][j][r] = 0.f;

    const int NT = PS / 64;

    for (int it = 0; it < NT; it++) {
        const int stage = it & 1;
        if (it + 1 < NT) {
            at_load_kv(sb + 2 * QTILE_B + (stage ^ 1) * 4 * KTILE_B,
                       khi, klo, vhi, vlo,
                       (bh * PS + (size_t)(it + 1) * 64) * PDK, tid);
            CP_COMMIT();
            CP_WAIT1();
        } else {
            CP_WAIT0();
        }
        __syncthreads();

        const uint32_t kb = sb + 2 * QTILE_B + stage * 4 * KTILE_B;
        const uint32_t sKh = kb + 0 * KTILE_B;
        const uint32_t sKl = kb + 1 * KTILE_B;
        const uint32_t sVh = kb + 2 * KTILE_B;
        const uint32_t sVl = kb + 3 * KTILE_B;

        // ---- S quadrant: 32 rows x 32 cols ----
        float sc[2][4][4];
#pragma unroll
        for (int i = 0; i < 2; i++)
#pragma unroll
            for (int j = 0; j < 4; j++)
#pragma unroll
                for (int r = 0; r < 4; r++) sc[i][j][r] = 0.f;

#pragma unroll
        for (int kk = 0; kk < 4; kk++) {
            const int kc = kk * 16;
            uint32_t qh[2][4], ql[2][4], kh[4][2], kl[4][2];
#pragma unroll
            for (int ma = 0; ma < 2; ma++) {
                uint32_t off = (uint32_t)((wm * 32 + ma * 16 + a_r) * (ASTR * 2) +
                                          (kc + a_c) * 2);
                ldsm_x4(qh[ma][0], qh[ma][1], qh[ma][2], qh[ma][3], sb + off);
                ldsm_x4(ql[ma][0], ql[ma][1], ql[ma][2], ql[ma][3],
                        sb + QTILE_B + off);
            }
#pragma unroll
            for (int nb2 = 0; nb2 < 2; nb2++) {
                uint32_t off = (uint32_t)((wn * 32 + nb2 * 16 + b_r) * (ASTR * 2) +
                                          (kc + b_c) * 2);
                ldsm_x4(kh[2 * nb2][0], kh[2 * nb2][1],
                        kh[2 * nb2 + 1][0], kh[2 * nb2 + 1][1], sKh + off);
                ldsm_x4(kl[2 * nb2][0], kl[2 * nb2][1],
                        kl[2 * nb2 + 1][0], kl[2 * nb2 + 1][1], sKl + off);
            }
#pragma unroll
            for (int ma = 0; ma < 2; ma++)
#pragma unroll
                for (int na = 0; na < 4; na++) {
                    mma_bf16(sc[ma][na], qh[ma], kh[na]);
                    mma_bf16(sc[ma][na], qh[ma], kl[na]);
                    mma_bf16(sc[ma][na], ql[ma], kh[na]);
                }
        }

        // ---- max-free base-2 softmax on the quadrant ----
#pragma unroll
        for (int ma = 0; ma < 2; ma++) {
            float rs0 = 0.f, rs1 = 0.f;
#pragma unroll
            for (int na = 0; na < 4; na++) {
                float p0 = exp2f(sc[ma][na][0]);
                float p1 = exp2f(sc[ma][na][1]);
                float p2 = exp2f(sc[ma][na][2]);
                float p3 = exp2f(sc[ma][na][3]);
                sc[ma][na][0] = p0; sc[ma][na][1] = p1;
                sc[ma][na][2] = p2; sc[ma][na][3] = p3;
                rs0 += p0 + p1;
                rs1 += p2 + p3;
            }
            l[ma][0] += rs0;
            l[ma][1] += rs1;
        }

        // ---- O += P V over this warp's KV half (full DK width) ----
#pragma unroll
        for (int kkh = 0; kkh < 2; kkh++) {
            uint32_t ph[2][4], pl[2][4];
#pragma unroll
            for (int ma = 0; ma < 2; ma++) {
                split2(sc[ma][2 * kkh][0],     sc[ma][2 * kkh][1],     ph[ma][0], pl[ma][0]);
                split2(sc[ma][2 * kkh][2],     sc[ma][2 * kkh][3],     ph[ma][1], pl[ma][1]);
                split2(sc[ma][2 * kkh + 1][0], sc[ma][2 * kkh + 1][1], ph[ma][2], pl[ma][2]);
                split2(sc[ma][2 * kkh + 1][2], sc[ma][2 * kkh + 1][3], ph[ma][3], pl[ma][3]);
            }
            const int g16 = wn * 2 + kkh;     // global k16 chunk within tile
#pragma unroll
            for (int dh = 0; dh < 2; dh++) {  // DK halves to cap live V regs
                uint32_t vh[4][2], vl[4][2];
#pragma unroll
                for (int db2 = 0; db2 < 2; db2++) {
                    uint32_t off = (uint32_t)((g16 * 16 + a_r) * (ASTR * 2) +
                                              ((dh * 2 + db2) * 16 + a_c) * 2);
                    ldsm_x4_t(vh[2 * db2][0], vh[2 * db2][1],
                              vh[2 * db2 + 1][0], vh[2 * db2 + 1][1], sVh + off);
                    ldsm_x4_t(vl[2 * db2][0], vl[2 * db2][1],
                              vl[2 * db2 + 1][0], vl[2 * db2 + 1][1], sVl + off);
                }
#pragma unroll
                for (int ma = 0; ma < 2; ma++)
#pragma unroll
                    for (int nb = 0; nb < 4; nb++) {
                        int od = dh * 4 + nb;
                        mma_bf16(oa[ma][od], ph[ma], vh[nb]);
                        mma_bf16(oa[ma][od], ph[ma], vl[nb]);
                        mma_bf16(oa[ma][od], pl[ma], vh[nb]);
                    }
            }
        }
        __syncthreads();
    }

    // ---- epilogue: additively combine wn pairs via smem, then store ----
    __syncthreads();
    float* xs = (float*)smem;                      // reuse tile smem
    const int slot = (wm * 32 + lane) * 69;        // 69 floats: 64 oa + 4 l
    if (wn == 1) {
        float* d = xs + slot;
        int idx = 0;
#pragma unroll
        for (int ma = 0; ma < 2; ma++)
#pragma unroll
            for (int nb = 0; nb < 8; nb++)
#pragma unroll
                for (int r = 0; r < 4; r++) d[idx++] = oa[ma][nb][r];
        d[64] = l[0][0]; d[65] = l[0][1]; d[66] = l[1][0]; d[67] = l[1][1];
    }
    __syncthreads();
    if (wn == 0) {
        const float* d = xs + slot;
        int idx = 0;
#pragma unroll
        for (int ma = 0; ma < 2; ma++)
#pragma unroll
            for (int nb = 0; nb < 8; nb++)
#pragma unroll
                for (int r = 0; r < 4; r++) oa[ma][nb][r] += d[idx++];
        l[0][0] += d[64]; l[0][1] += d[65]; l[1][0] += d[66]; l[1][1] += d[67];

#pragma unroll
        for (int ma = 0; ma < 2; ma++) {
#pragma unroll
            for (int half = 0; half < 2; half++) {
                float lt = l[ma][half];
                lt += __shfl_xor_sync(0xFFFFFFFFu, lt, 1);
                lt += __shfl_xor_sync(0xFFFFFFFFu, lt, 2);
                float invl = 1.0f / lt;
                int t = t0 + wm * 32 + ma * 16 + half * 8 + (lane >> 2);
                size_t base = ((size_t)(b * PT + t)) * PD + h * PDK;
#pragma unroll
                for (int nb = 0; nb < 8; nb++) {
                    int col = nb * 8 + 2 * (lane & 3);
                    float v0 = oa[ma][nb][half * 2 + 0] * invl;
                    float v1 = oa[ma][nb][half * 2 + 1] * invl;
                    uint32_t hp, lp;
                    split2(v0, v1, hp, lp);
                    *(uint32_t*)(ohi + base + col) = hp;
                    *(uint32_t*)(olo + base + col) = lp;
                }
            }
        }
    }
}

// ---------------------------------------------------------------------------
extern "C" void kernel_launch(void* const* d_in, const int* in_sizes, int n_in,
                              void* d_out, int out_size)
{
    const float* query = (const float*)d_in[0];
    const float* value = (const float*)d_in[1];
    const float* key   = (const float*)d_in[2];
    const float* Wq    = (const float*)d_in[3];
    const float* bq    = (const float*)d_in[4];
    const float* Wk    = (const float*)d_in[5];
    const float* bk    = (const float*)d_in[6];
    const float* Wv    = (const float*)d_in[7];
    const float* bv    = (const float*)d_in[8];
    const float* Wo    = (const float*)d_in[9];
    const float* bo    = (const float*)d_in[10];
    float* out = (float*)d_out;

    __nv_bfloat16 *qhi, *qlo, *khi, *klo, *vhi, *vlo, *ahi, *alo;
    __nv_bfloat16 *pah, *pal, *pbh, *pbl;
    cudaGetSymbolAddress((void**)&qhi, g_qhi);
    cudaGetSymbolAddress((void**)&qlo, g_qlo);
    cudaGetSymbolAddress((void**)&khi, g_khi);
    cudaGetSymbolAddress((void**)&klo, g_klo);
    cudaGetSymbolAddress((void**)&vhi, g_vhi);
    cudaGetSymbolAddress((void**)&vlo, g_vlo);
    cudaGetSymbolAddress((void**)&ahi, g_ahi);
    cudaGetSymbolAddress((void**)&alo, g_alo);
    cudaGetSymbolAddress((void**)&pah, g_pa_hi);
    cudaGetSymbolAddress((void**)&pal, g_pa_lo);
    cudaGetSymbolAddress((void**)&pbh, g_pb_hi);
    cudaGetSymbolAddress((void**)&pbl, g_pb_lo);

    const size_t PA = (size_t)GEMM_M * GEMM_K;
    const size_t PBW = (size_t)GEMM_N * GEMM_K;

    cudaFuncSetAttribute(proj_gemm3_kernel,
                         cudaFuncAttributeMaxDynamicSharedMemorySize, GSM_TOTAL);
    cudaFuncSetAttribute(out_gemm_kernel,
                         cudaFuncAttributeMaxDynamicSharedMemorySize, GSM_TOTAL);
    cudaFuncSetAttribute(attn_mma_kernel,
                         cudaFuncAttributeMaxDynamicSharedMemorySize, AT_SMEM);

    SplitAParams SA;
    SA.x[0] = query; SA.x[1] = key; SA.x[2] = value;
    for (int z = 0; z < 3; z++) {
        SA.hi[z] = pah + z * PA;
        SA.lo[z] = pal + z * PA;
    }
    split_a3_kernel<<<dim3(GEMM_M * GEMM_K / 4 / 1024, 1, 3), 256>>>(SA);

    SplitWParams SW;
    SW.w[0] = Wq; SW.w[1] = Wk; SW.w[2] = Wv; SW.w[3] = Wo;
    for (int z = 0; z < 4; z++) {
        SW.hi[z] = pbh + z * PBW;
        SW.lo[z] = pbl + z * PBW;
    }
    split_w4_kernel<<<dim3(GEMM_N / 32, GEMM_K / 32, 4), dim3(32, 8)>>>(SW);

    ProjParams PP;
    for (int z = 0; z < 3; z++) {
        PP.ah[z] = pah + z * PA;
        PP.al[z] = pal + z * PA;
        PP.bh[z] = pbh + z * PBW;
        PP.bl[z] = pbl + z * PBW;
    }
    PP.bias[0] = bq; PP.bias[1] = bk; PP.bias[2] = bv;
    PP.ch[0] = qhi; PP.cl[0] = qlo;
    PP.ch[1] = khi; PP.cl[1] = klo;
    PP.ch[2] = vhi; PP.cl[2] = vlo;
    PP.scale[0] = 0.125f * 1.4426950408889634f;  // 1/sqrt(DK) * log2(e)
    PP.scale[1] = 1.0f;
    PP.scale[2] = 1.0f;
    proj_gemm3_kernel<<<dim3(GEMM_N / 128, GEMM_M / 128, 3), 256, GSM_TOTAL>>>(PP);

    attn_mma_kernel<<<dim3(PT / 128, PH, PB), 256, AT_SMEM>>>(
        qhi, qlo, khi, klo, vhi, vlo, ahi, alo);

    out_gemm_kernel<<<dim3(GEMM_N / 128, GEMM_M / 128), 256, GSM_TOTAL>>>(
        ahi, alo, pbh + 3 * PBW, pbl + 3 * PBW, bo, out);
}

// round 15
// speedup vs baseline: 1.0307x; 1.0307x over previous
#include <cuda_runtime.h>
#include <cuda_bf16.h>
#include <math.h>
#include <stdint.h>

// Problem constants
constexpr int PB = 2;      // batch
constexpr int PT = 2048;   // query seq
constexpr int PS = 2048;   // key/value seq
constexpr int PD = 1024;   // model dim
constexpr int PH = 16;     // heads
constexpr int PDK = 64;    // head dim

constexpr int GEMM_M = PB * PT;  // 4096
constexpr int GEMM_N = PD;       // 1024
constexpr int GEMM_K = PD;       // 1024

// ---------------------------------------------------------------------------
// Scratch (device globals — no allocation allowed)
// ---------------------------------------------------------------------------
__device__ __nv_bfloat16 g_qhi[(size_t)PB * PH * PT * PDK];
__device__ __nv_bfloat16 g_qlo[(size_t)PB * PH * PT * PDK];
__device__ __nv_bfloat16 g_khi[(size_t)PB * PH * PS * PDK];
__device__ __nv_bfloat16 g_klo[(size_t)PB * PH * PS * PDK];
__device__ __nv_bfloat16 g_vhi[(size_t)PB * PH * PS * PDK];
__device__ __nv_bfloat16 g_vlo[(size_t)PB * PH * PS * PDK];

__device__ __nv_bfloat16 g_pa_hi[3][(size_t)GEMM_M * GEMM_K];
__device__ __nv_bfloat16 g_pa_lo[3][(size_t)GEMM_M * GEMM_K];
__device__ __nv_bfloat16 g_pb_hi[4][(size_t)GEMM_N * GEMM_K];
__device__ __nv_bfloat16 g_pb_lo[4][(size_t)GEMM_N * GEMM_K];
__device__ __nv_bfloat16 g_ahi[(size_t)GEMM_M * GEMM_K];
__device__ __nv_bfloat16 g_alo[(size_t)GEMM_M * GEMM_K];

// ---------------------------------------------------------------------------
// PTX helpers (base ISA only)
// ---------------------------------------------------------------------------
__device__ __forceinline__ uint32_t smem_u32(const void* p) {
    uint32_t a;
    asm("{ .reg .u64 t; cvta.to.shared.u64 t, %1; cvt.u32.u64 %0, t; }"
        : "=r"(a) : "l"(p));
    return a;
}

__device__ __forceinline__ void cp16(uint32_t saddr, const void* gaddr) {
    asm volatile("cp.async.cg.shared.global [%0], [%1], 16;"
                 :: "r"(saddr), "l"(gaddr) : "memory");
}
#define CP_COMMIT() asm volatile("cp.async.commit_group;" ::: "memory")
#define CP_WAIT1()  asm volatile("cp.async.wait_group 1;" ::: "memory")
#define CP_WAIT0()  asm volatile("cp.async.wait_group 0;" ::: "memory")

__device__ __forceinline__ void ldsm_x4(uint32_t& r0, uint32_t& r1,
                                        uint32_t& r2, uint32_t& r3,
                                        uint32_t addr) {
    asm volatile("ldmatrix.sync.aligned.m8n8.x4.shared.b16 {%0,%1,%2,%3}, [%4];"
                 : "=r"(r0), "=r"(r1), "=r"(r2), "=r"(r3) : "r"(addr));
}

__device__ __forceinline__ void ldsm_x4_t(uint32_t& r0, uint32_t& r1,
                                          uint32_t& r2, uint32_t& r3,
                                          uint32_t addr) {
    asm volatile("ldmatrix.sync.aligned.m8n8.x4.trans.shared.b16 {%0,%1,%2,%3}, [%4];"
                 : "=r"(r0), "=r"(r1), "=r"(r2), "=r"(r3) : "r"(addr));
}

__device__ __forceinline__ void mma_bf16(float* d, const uint32_t* a,
                                         const uint32_t* b) {
    asm volatile(
        "mma.sync.aligned.m16n8k16.row.col.f32.bf16.bf16.f32 "
        "{%0,%1,%2,%3}, {%4,%5,%6,%7}, {%8,%9}, {%0,%1,%2,%3};"
        : "+f"(d[0]), "+f"(d[1]), "+f"(d[2]), "+f"(d[3])
        : "r"(a[0]), "r"(a[1]), "r"(a[2]), "r"(a[3]),
          "r"(b[0]), "r"(b[1]));
}

// split (a, b) fp32 pair into packed bf16x2 hi + bf16x2 lo
__device__ __forceinline__ void split2(float a, float b,
                                       uint32_t& hi, uint32_t& lo) {
    __nv_bfloat16 ha = __float2bfloat16(a);
    __nv_bfloat16 hb = __float2bfloat16(b);
    hi = ((uint32_t)__bfloat16_as_ushort(hb) << 16) |
         (uint32_t)__bfloat16_as_ushort(ha);
    __nv_bfloat162 r = __floats2bfloat162_rn(a - __bfloat162float(ha),
                                             b - __bfloat162float(hb));
    lo = *reinterpret_cast<uint32_t*>(&r);
}

// ---------------------------------------------------------------------------
// Split kernels (fused over z planes)
// ---------------------------------------------------------------------------
struct SplitAParams {
    const float* x[3];
    __nv_bfloat16* hi[3];
    __nv_bfloat16* lo[3];
};

__global__ __launch_bounds__(256) void split_a3_kernel(SplitAParams P)
{
    const int z = blockIdx.z;
    const float4* xp = (const float4*)P.x[z];
    uint32_t* hp = (uint32_t*)P.hi[z];
    uint32_t* lp = (uint32_t*)P.lo[z];
    const int base = blockIdx.x * 1024 + threadIdx.x;

    float4 v[4];
#pragma unroll
    for (int j = 0; j < 4; j++) v[j] = xp[base + j * 256];

#pragma unroll
    for (int j = 0; j < 4; j++) {
        int i = base + j * 256;
        uint32_t h0, l0, h1, l1;
        split2(v[j].x, v[j].y, h0, l0);
        split2(v[j].z, v[j].w, h1, l1);
        hp[2 * i + 0] = h0;
        hp[2 * i + 1] = h1;
        lp[2 * i + 0] = l0;
        lp[2 * i + 1] = l1;
    }
}

struct SplitWParams {
    const float* w[4];
    __nv_bfloat16* hi[4];
    __nv_bfloat16* lo[4];
};

__global__ __launch_bounds__(256) void split_w4_kernel(SplitWParams P)
{
    __shared__ float t[32][33];
    int z = blockIdx.z;
    const float* W = P.w[z];
    __nv_bfloat16* hi = P.hi[z];
    __nv_bfloat16* lo = P.lo[z];
    int n0 = blockIdx.x * 32, k0 = blockIdx.y * 32;
    int tx = threadIdx.x, ty = threadIdx.y;
#pragma unroll
    for (int i = 0; i < 32; i += 8)
        t[ty + i][tx] = W[(size_t)(k0 + ty + i) * GEMM_N + n0 + tx];
    __syncthreads();
#pragma unroll
    for (int i = 0; i < 32; i += 8) {
        float v = t[tx][ty + i];
        __nv_bfloat16 h = __float2bfloat16(v);
        size_t o = (size_t)(n0 + ty + i) * GEMM_K + k0 + tx;
        hi[o] = h;
        lo[o] = __float2bfloat16(v - __bfloat162float(h));
    }
}

// ---------------------------------------------------------------------------
// HMMA GEMM core: 128x128 block, BK=32, NEW: 4 warps (2M x 2N), warp tile
// 64x64 — halves B-fragment duplication (crossbar traffic 96->64 KB/chunk).
// 128-thread CTA, (128,2) -> 2 CTAs/SM with reg cap 256 (no spills).
// ---------------------------------------------------------------------------
constexpr int GBK = 32;
constexpr int GSTR = 40;
constexpr int GTILE_B = 128 * GSTR * 2;         // 10240
constexpr int GSTAGE_B = 4 * GTILE_B;           // 40960
constexpr int GSM_TOTAL = 2 * GSTAGE_B;         // 81920
constexpr int GNCH = GEMM_K / GBK;              // 32

__device__ __forceinline__ void g_load_tile(
    uint32_t sdst, const __nv_bfloat16* __restrict__ g, int row0, int k0, int tid)
{
    // 128 rows x 32 bf16 = 4 x 16B segs/row; 512 segs / 128 thr = 4 each
#pragma unroll
    for (int i = 0; i < 4; i++) {
        int s = tid + i * 128;
        int r = s >> 2;
        int c = s & 3;
        cp16(sdst + (uint32_t)(r * (GSTR * 2) + c * 16),
             g + (size_t)(row0 + r) * GEMM_K + k0 + c * 8);
    }
}

__device__ __forceinline__ void g_load_stage(
    uint32_t st, const __nv_bfloat16* Ahi, const __nv_bfloat16* Alo,
    const __nv_bfloat16* Bhi, const __nv_bfloat16* Blo,
    int bm, int bn, int k0, int tid)
{
    g_load_tile(st + 0 * GTILE_B, Ahi, bm, k0, tid);
    g_load_tile(st + 1 * GTILE_B, Alo, bm, k0, tid);
    g_load_tile(st + 2 * GTILE_B, Bhi, bn, k0, tid);
    g_load_tile(st + 3 * GTILE_B, Blo, bn, k0, tid);
    CP_COMMIT();
}

__device__ __forceinline__ void gemm_core(
    uint32_t sb, int tid,
    const __nv_bfloat16* __restrict__ Ahi, const __nv_bfloat16* __restrict__ Alo,
    const __nv_bfloat16* __restrict__ Bhi, const __nv_bfloat16* __restrict__ Blo,
    int bm, int bn, float acc[4][8][4])
{
    const int lane = tid & 31;
    const int wid = tid >> 5;       // 0..3
    const int wm = wid >> 1;        // 0..1 (64-row slice)
    const int wn = wid & 1;         // 0..1 (64-col slice)

    const int a_r = ((lane >> 3) & 1) * 8 + (lane & 7);
    const int a_c = (lane >> 4) * 8;
    const int b_r = (lane >> 4) * 8 + (lane & 7);
    const int b_c = ((lane >> 3) & 1) * 8;

    g_load_stage(sb, Ahi, Alo, Bhi, Blo, bm, bn, 0, tid);

    for (int c = 0; c < GNCH; c++) {
        if (c + 1 < GNCH) {
            g_load_stage(sb + ((c + 1) & 1) * GSTAGE_B, Ahi, Alo, Bhi, Blo,
                         bm, bn, (c + 1) * GBK, tid);
            CP_WAIT1();
        } else {
            CP_WAIT0();
        }
        __syncthreads();

        const uint32_t st = sb + (c & 1) * GSTAGE_B;
        const uint32_t sAhi = st + 0 * GTILE_B;
        const uint32_t sAlo = st + 1 * GTILE_B;
        const uint32_t sBhi = st + 2 * GTILE_B;
        const uint32_t sBlo = st + 3 * GTILE_B;

#pragma unroll
        for (int ks = 0; ks < 2; ks++) {
            const int kc = ks * 16;
            uint32_t ah[4][4], al[4][4];
#pragma unroll
            for (int ma = 0; ma < 4; ma++) {
                uint32_t off =
                    (uint32_t)((wm * 64 + ma * 16 + a_r) * (GSTR * 2) +
                               (kc + a_c) * 2);
                ldsm_x4(ah[ma][0], ah[ma][1], ah[ma][2], ah[ma][3], sAhi + off);
                ldsm_x4(al[ma][0], al[ma][1], al[ma][2], al[ma][3], sAlo + off);
            }
#pragma unroll
            for (int h2 = 0; h2 < 2; h2++) {
                uint32_t bh[4][2], bl[4][2];
#pragma unroll
                for (int pa = 0; pa < 2; pa++) {
                    uint32_t off =
                        (uint32_t)((wn * 64 + (h2 * 2 + pa) * 16 + b_r) *
                                       (GSTR * 2) +
                                   (kc + b_c) * 2);
                    ldsm_x4(bh[2 * pa][0], bh[2 * pa][1],
                            bh[2 * pa + 1][0], bh[2 * pa + 1][1], sBhi + off);
                    ldsm_x4(bl[2 * pa][0], bl[2 * pa][1],
                            bl[2 * pa + 1][0], bl[2 * pa + 1][1], sBlo + off);
                }
#pragma unroll
                for (int ma = 0; ma < 4; ma++)
#pragma unroll
                    for (int nb = 0; nb < 4; nb++) {
                        int na = h2 * 4 + nb;
                        mma_bf16(acc[ma][na], ah[ma], bh[nb]);
                        mma_bf16(acc[ma][na], ah[ma], bl[nb]);
                        mma_bf16(acc[ma][na], al[ma], bh[nb]);
                    }
            }
        }
        __syncthreads();
    }
}

struct ProjParams {
    const __nv_bfloat16* ah[3];
    const __nv_bfloat16* al[3];
    const __nv_bfloat16* bh[3];
    const __nv_bfloat16* bl[3];
    const float* bias[3];
    __nv_bfloat16* ch[3];
    __nv_bfloat16* cl[3];
    float scale[3];
};

__global__ __launch_bounds__(128, 2) void proj_gemm3_kernel(ProjParams P)
{
    extern __shared__ __align__(128) char smem[];
    const uint32_t sb = smem_u32(smem);
    const int tid = threadIdx.x;
    const int z = blockIdx.z;
    const int bm = blockIdx.y * 128;
    const int bn = blockIdx.x * 128;

    float acc[4][8][4];
#pragma unroll
    for (int i = 0; i < 4; i++)
#pragma unroll
        for (int j = 0; j < 8; j++)
#pragma unroll
            for (int r = 0; r < 4; r++) acc[i][j][r] = 0.f;

    gemm_core(sb, tid, P.ah[z], P.al[z], P.bh[z], P.bl[z], bm, bn, acc);

    const float* bias = P.bias[z];
    const float scl = P.scale[z];
    __nv_bfloat16* Chi = P.ch[z];
    __nv_bfloat16* Clo = P.cl[z];
    const int wid = tid >> 5;
    const int lane = tid & 31;
    const int wm = wid >> 1;
    const int wn = wid & 1;
    const int lr = lane >> 2;
    const int lc = (lane & 3) * 2;
#pragma unroll
    for (int ma = 0; ma < 4; ma++) {
#pragma unroll
        for (int half = 0; half < 2; half++) {
            int row = bm + wm * 64 + ma * 16 + half * 8 + lr;
            int b = row / PT;
            int t = row - b * PT;
#pragma unroll
            for (int na = 0; na < 8; na++) {
                int col = bn + wn * 64 + na * 8 + lc;
                float v0 = (acc[ma][na][half * 2 + 0] + bias[col + 0]) * scl;
                float v1 = (acc[ma][na][half * 2 + 1] + bias[col + 1]) * scl;
                int h = col >> 6;
                int dk = col & 63;
                size_t o = (((size_t)(b * PH + h) * PT) + t) * PDK + dk;
                uint32_t hp, lp;
                split2(v0, v1, hp, lp);
                *(uint32_t*)(Chi + o) = hp;
                *(uint32_t*)(Clo + o) = lp;
            }
        }
    }
}

__global__ __launch_bounds__(128, 2) void out_gemm_kernel(
    const __nv_bfloat16* __restrict__ Ahi, const __nv_bfloat16* __restrict__ Alo,
    const __nv_bfloat16* __restrict__ Bhi, const __nv_bfloat16* __restrict__ Blo,
    const float* __restrict__ bias, float* __restrict__ C)
{
    extern __shared__ __align__(128) char smem[];
    const uint32_t sb = smem_u32(smem);
    const int tid = threadIdx.x;
    const int bm = blockIdx.y * 128;
    const int bn = blockIdx.x * 128;

    float acc[4][8][4];
#pragma unroll
    for (int i = 0; i < 4; i++)
#pragma unroll
        for (int j = 0; j < 8; j++)
#pragma unroll
            for (int r = 0; r < 4; r++) acc[i][j][r] = 0.f;

    gemm_core(sb, tid, Ahi, Alo, Bhi, Blo, bm, bn, acc);

    const int wid = tid >> 5;
    const int lane = tid & 31;
    const int wm = wid >> 1;
    const int wn = wid & 1;
    const int lr = lane >> 2;
    const int lc = (lane & 3) * 2;
#pragma unroll
    for (int ma = 0; ma < 4; ma++) {
#pragma unroll
        for (int half = 0; half < 2; half++) {
            int row = bm + wm * 64 + ma * 16 + half * 8 + lr;
#pragma unroll
            for (int na = 0; na < 8; na++) {
                int col = bn + wn * 64 + na * 8 + lc;
                float v0 = acc[ma][na][half * 2 + 0] + bias[col + 0];
                float v1 = acc[ma][na][half * 2 + 1] + bias[col + 1];
                float2* dst = (float2*)(C + (size_t)row * GEMM_N + col);
                *dst = make_float2(v0, v1);
            }
        }
    }
}

// ---------------------------------------------------------------------------
// Flash attention on mma.sync, full hi/lo, max-free base-2 softmax.
// Measured-good Round-13 config (128 threads, 32-row warp tiles) — verbatim.
// ---------------------------------------------------------------------------
constexpr int ASTR = 72;
constexpr int QTILE_B = 128 * ASTR * 2;
constexpr int KTILE_B = 64 * ASTR * 2;
constexpr int AT_SMEM = 2 * QTILE_B + 2 * 4 * KTILE_B;  // 110592

__device__ __forceinline__ void at_load_kv(
    uint32_t base, const __nv_bfloat16* kh, const __nv_bfloat16* kl,
    const __nv_bfloat16* vh, const __nv_bfloat16* vl,
    size_t gbase, int tid)
{
#pragma unroll
    for (int i = 0; i < 4; i++) {
        int s = tid + i * 128;
        int r = s >> 3;
        int c = s & 7;
        uint32_t doff = (uint32_t)(r * (ASTR * 2) + c * 16);
        size_t goff = gbase + (size_t)r * PDK + c * 8;
        cp16(base + 0 * KTILE_B + doff, kh + goff);
        cp16(base + 1 * KTILE_B + doff, kl + goff);
        cp16(base + 2 * KTILE_B + doff, vh + goff);
        cp16(base + 3 * KTILE_B + doff, vl + goff);
    }
}

__global__ __launch_bounds__(128, 1) void attn_mma_kernel(
    const __nv_bfloat16* __restrict__ qhi, const __nv_bfloat16* __restrict__ qlo,
    const __nv_bfloat16* __restrict__ khi, const __nv_bfloat16* __restrict__ klo,
    const __nv_bfloat16* __restrict__ vhi, const __nv_bfloat16* __restrict__ vlo,
    __nv_bfloat16* __restrict__ ohi, __nv_bfloat16* __restrict__ olo)
{
    extern __shared__ __align__(128) char smem[];
    const uint32_t sb = smem_u32(smem);
    const int tid = threadIdx.x;
    const int w = tid >> 5;
    const int lane = tid & 31;
    const int t0 = blockIdx.x * 128;
    const int h = blockIdx.y;
    const int b = blockIdx.z;
    const size_t bh = (size_t)(b * PH + h);

    const int a_r = ((lane >> 3) & 1) * 8 + (lane & 7);
    const int a_c = (lane >> 4) * 8;
    const int b_r = (lane >> 4) * 8 + (lane & 7);
    const int b_c = ((lane >> 3) & 1) * 8;

    {
        const __nv_bfloat16* qhb = qhi + (bh * PT + t0) * PDK;
        const __nv_bfloat16* qlb = qlo + (bh * PT + t0) * PDK;
#pragma unroll
        for (int i = 0; i < 8; i++) {
            int s = tid + i * 128;
            int r = s >> 3;
            int c = s & 7;
            uint32_t doff = (uint32_t)(r * (ASTR * 2) + c * 16);
            cp16(sb + doff, qhb + (size_t)r * PDK + c * 8);
            cp16(sb + QTILE_B + doff, qlb + (size_t)r * PDK + c * 8);
        }
        at_load_kv(sb + 2 * QTILE_B, khi, klo, vhi, vlo, bh * PS * PDK, tid);
        CP_COMMIT();
    }

    float l[2][2];
    float oa[2][8][4];
#pragma unroll
    for (int i = 0; i < 2; i++)
#pragma unroll
        for (int j = 0; j < 2; j++) l[i][j] = 0.f;
#pragma unroll
    for (int i = 0; i < 2; i++)
#pragma unroll
        for (int j = 0; j < 8; j++)
#pragma unroll
            for (int r = 0; r < 4; r++) oa[i][j][r] = 0.f;

    const int NT = PS / 64;

    for (int it = 0; it < NT; it++) {
        const int stage = it & 1;
        if (it + 1 < NT) {
            at_load_kv(sb + 2 * QTILE_B + (stage ^ 1) * 4 * KTILE_B,
                       khi, klo, vhi, vlo,
                       (bh * PS + (size_t)(it + 1) * 64) * PDK, tid);
            CP_COMMIT();
            CP_WAIT1();
        } else {
            CP_WAIT0();
        }
        __syncthreads();

        const uint32_t kb = sb + 2 * QTILE_B + stage * 4 * KTILE_B;
        const uint32_t sKh = kb + 0 * KTILE_B;
        const uint32_t sKl = kb + 1 * KTILE_B;
        const uint32_t sVh = kb + 2 * KTILE_B;
        const uint32_t sVl = kb + 3 * KTILE_B;

        float sc[2][8][4];
#pragma unroll
        for (int i = 0; i < 2; i++)
#pragma unroll
            for (int j = 0; j < 8; j++)
#pragma unroll
                for (int r = 0; r < 4; r++) sc[i][j][r] = 0.f;

#pragma unroll
        for (int kk = 0; kk < 4; kk++) {
            const int kc = kk * 16;
            uint32_t qh[2][4], ql[2][4], kh[8][2], kl[8][2];
#pragma unroll
            for (int ma = 0; ma < 2; ma++) {
                uint32_t off = (uint32_t)((w * 32 + ma * 16 + a_r) * (ASTR * 2) +
                                          (kc + a_c) * 2);
                ldsm_x4(qh[ma][0], qh[ma][1], qh[ma][2], qh[ma][3], sb + off);
                ldsm_x4(ql[ma][0], ql[ma][1], ql[ma][2], ql[ma][3],
                        sb + QTILE_B + off);
            }
#pragma unroll
            for (int nb = 0; nb < 4; nb++) {
                uint32_t off = (uint32_t)((nb * 16 + b_r) * (ASTR * 2) +
                                          (kc + b_c) * 2);
                ldsm_x4(kh[2 * nb][0], kh[2 * nb][1],
                        kh[2 * nb + 1][0], kh[2 * nb + 1][1], sKh + off);
                ldsm_x4(kl[2 * nb][0], kl[2 * nb][1],
                        kl[2 * nb + 1][0], kl[2 * nb + 1][1], sKl + off);
            }
#pragma unroll
            for (int ma = 0; ma < 2; ma++)
#pragma unroll
                for (int na = 0; na < 8; na++) {
                    mma_bf16(sc[ma][na], qh[ma], kh[na]);
                    mma_bf16(sc[ma][na], qh[ma], kl[na]);
                    mma_bf16(sc[ma][na], ql[ma], kh[na]);
                }
        }

        // ---- max-free base-2 softmax (lane-partial l) ----
#pragma unroll
        for (int ma = 0; ma < 2; ma++) {
            float rs0 = 0.f, rs1 = 0.f;
#pragma unroll
            for (int na = 0; na < 8; na++) {
                float p0 = exp2f(sc[ma][na][0]);
                float p1 = exp2f(sc[ma][na][1]);
                float p2 = exp2f(sc[ma][na][2]);
                float p3 = exp2f(sc[ma][na][3]);
                sc[ma][na][0] = p0; sc[ma][na][1] = p1;
                sc[ma][na][2] = p2; sc[ma][na][3] = p3;
                rs0 += p0 + p1;
                rs1 += p2 + p3;
            }
            l[ma][0] += rs0;
            l[ma][1] += rs1;
        }

        // ---- O += P V ----
#pragma unroll
        for (int kk = 0; kk < 4; kk++) {
            uint32_t ph[2][4], pl[2][4];
#pragma unroll
            for (int ma = 0; ma < 2; ma++) {
                split2(sc[ma][2 * kk][0],     sc[ma][2 * kk][1],     ph[ma][0], pl[ma][0]);
                split2(sc[ma][2 * kk][2],     sc[ma][2 * kk][3],     ph[ma][1], pl[ma][1]);
                split2(sc[ma][2 * kk + 1][0], sc[ma][2 * kk + 1][1], ph[ma][2], pl[ma][2]);
                split2(sc[ma][2 * kk + 1][2], sc[ma][2 * kk + 1][3], ph[ma][3], pl[ma][3]);
            }
            uint32_t vh[8][2], vl[8][2];
#pragma unroll
            for (int db = 0; db < 4; db++) {
                uint32_t off = (uint32_t)((kk * 16 + a_r) * (ASTR * 2) +
                                          (db * 16 + a_c) * 2);
                ldsm_x4_t(vh[2 * db][0], vh[2 * db][1],
                          vh[2 * db + 1][0], vh[2 * db + 1][1], sVh + off);
                ldsm_x4_t(vl[2 * db][0], vl[2 * db][1],
                          vl[2 * db + 1][0], vl[2 * db + 1][1], sVl + off);
            }
#pragma unroll
            for (int ma = 0; ma < 2; ma++)
#pragma unroll
                for (int nb = 0; nb < 8; nb++) {
                    mma_bf16(oa[ma][nb], ph[ma], vh[nb]);
                    mma_bf16(oa[ma][nb], ph[ma], vl[nb]);
                    mma_bf16(oa[ma][nb], pl[ma], vh[nb]);
                }
        }
        __syncthreads();
    }

    // ---- epilogue ----
#pragma unroll
    for (int ma = 0; ma < 2; ma++) {
#pragma unroll
        for (int half = 0; half < 2; half++) {
            float lt = l[ma][half];
            lt += __shfl_xor_sync(0xFFFFFFFFu, lt, 1);
            lt += __shfl_xor_sync(0xFFFFFFFFu, lt, 2);
            float invl = 1.0f / lt;
            int t = t0 + w * 32 + ma * 16 + half * 8 + (lane >> 2);
            size_t base = ((size_t)(b * PT + t)) * PD + h * PDK;
#pragma unroll
            for (int nb = 0; nb < 8; nb++) {
                int col = nb * 8 + 2 * (lane & 3);
                float v0 = oa[ma][nb][half * 2 + 0] * invl;
                float v1 = oa[ma][nb][half * 2 + 1] * invl;
                uint32_t hp, lp;
                split2(v0, v1, hp, lp);
                *(uint32_t*)(ohi + base + col) = hp;
                *(uint32_t*)(olo + base + col) = lp;
            }
        }
    }
}

// ---------------------------------------------------------------------------
extern "C" void kernel_launch(void* const* d_in, const int* in_sizes, int n_in,
                              void* d_out, int out_size)
{
    const float* query = (const float*)d_in[0];
    const float* value = (const float*)d_in[1];
    const float* key   = (const float*)d_in[2];
    const float* Wq    = (const float*)d_in[3];
    const float* bq    = (const float*)d_in[4];
    const float* Wk    = (const float*)d_in[5];
    const float* bk    = (const float*)d_in[6];
    const float* Wv    = (const float*)d_in[7];
    const float* bv    = (const float*)d_in[8];
    const float* Wo    = (const float*)d_in[9];
    const float* bo    = (const float*)d_in[10];
    float* out = (float*)d_out;

    __nv_bfloat16 *qhi, *qlo, *khi, *klo, *vhi, *vlo, *ahi, *alo;
    __nv_bfloat16 *pah, *pal, *pbh, *pbl;
    cudaGetSymbolAddress((void**)&qhi, g_qhi);
    cudaGetSymbolAddress((void**)&qlo, g_qlo);
    cudaGetSymbolAddress((void**)&khi, g_khi);
    cudaGetSymbolAddress((void**)&klo, g_klo);
    cudaGetSymbolAddress((void**)&vhi, g_vhi);
    cudaGetSymbolAddress((void**)&vlo, g_vlo);
    cudaGetSymbolAddress((void**)&ahi, g_ahi);
    cudaGetSymbolAddress((void**)&alo, g_alo);
    cudaGetSymbolAddress((void**)&pah, g_pa_hi);
    cudaGetSymbolAddress((void**)&pal, g_pa_lo);
    cudaGetSymbolAddress((void**)&pbh, g_pb_hi);
    cudaGetSymbolAddress((void**)&pbl, g_pb_lo);

    const size_t PA = (size_t)GEMM_M * GEMM_K;
    const size_t PBW = (size_t)GEMM_N * GEMM_K;

    cudaFuncSetAttribute(proj_gemm3_kernel,
                         cudaFuncAttributeMaxDynamicSharedMemorySize, GSM_TOTAL);
    cudaFuncSetAttribute(out_gemm_kernel,
                         cudaFuncAttributeMaxDynamicSharedMemorySize, GSM_TOTAL);
    cudaFuncSetAttribute(attn_mma_kernel,
                         cudaFuncAttributeMaxDynamicSharedMemorySize, AT_SMEM);

    SplitAParams SA;
    SA.x[0] = query; SA.x[1] = key; SA.x[2] = value;
    for (int z = 0; z < 3; z++) {
        SA.hi[z] = pah + z * PA;
        SA.lo[z] = pal + z * PA;
    }
    split_a3_kernel<<<dim3(GEMM_M * GEMM_K / 4 / 1024, 1, 3), 256>>>(SA);

    SplitWParams SW;
    SW.w[0] = Wq; SW.w[1] = Wk; SW.w[2] = Wv; SW.w[3] = Wo;
    for (int z = 0; z < 4; z++) {
        SW.hi[z] = pbh + z * PBW;
        SW.lo[z] = pbl + z * PBW;
    }
    split_w4_kernel<<<dim3(GEMM_N / 32, GEMM_K / 32, 4), dim3(32, 8)>>>(SW);

    ProjParams PP;
    for (int z = 0; z < 3; z++) {
        PP.ah[z] = pah + z * PA;
        PP.al[z] = pal + z * PA;
        PP.bh[z] = pbh + z * PBW;
        PP.bl[z] = pbl + z * PBW;
    }
    PP.bias[0] = bq; PP.bias[1] = bk; PP.bias[2] = bv;
    PP.ch[0] = qhi; PP.cl[0] = qlo;
    PP.ch[1] = khi; PP.cl[1] = klo;
    PP.ch[2] = vhi; PP.cl[2] = vlo;
    PP.scale[0] = 0.125f * 1.4426950408889634f;  // 1/sqrt(DK) * log2(e)
    PP.scale[1] = 1.0f;
    PP.scale[2] = 1.0f;
    proj_gemm3_kernel<<<dim3(GEMM_N / 128, GEMM_M / 128, 3), 128, GSM_TOTAL>>>(PP);

    attn_mma_kernel<<<dim3(PT / 128, PH, PB), 128, AT_SMEM>>>(
        qhi, qlo, khi, klo, vhi, vlo, ahi, alo);

    out_gemm_kernel<<<dim3(GEMM_N / 128, GEMM_M / 128), 128, GSM_TOTAL>>>(
        ahi, alo, pbh + 3 * PBW, pbl + 3 * PBW, bo, out);
}

// round 16
// speedup vs baseline: 1.0827x; 1.0505x over previous
#include <cuda_runtime.h>
#include <cuda_bf16.h>
#include <math.h>
#include <stdint.h>

// Problem constants
constexpr int PB = 2;      // batch
constexpr int PT = 2048;   // query seq
constexpr int PS = 2048;   // key/value seq
constexpr int PD = 1024;   // model dim
constexpr int PH = 16;     // heads
constexpr int PDK = 64;    // head dim

constexpr int GEMM_M = PB * PT;  // 4096
constexpr int GEMM_N = PD;       // 1024
constexpr int GEMM_K = PD;       // 1024

// ---------------------------------------------------------------------------
// Scratch (device globals — no allocation allowed)
// ---------------------------------------------------------------------------
__device__ __nv_bfloat16 g_qhi[(size_t)PB * PH * PT * PDK];
__device__ __nv_bfloat16 g_qlo[(size_t)PB * PH * PT * PDK];
__device__ __nv_bfloat16 g_khi[(size_t)PB * PH * PS * PDK];
__device__ __nv_bfloat16 g_klo[(size_t)PB * PH * PS * PDK];
__device__ __nv_bfloat16 g_vhi[(size_t)PB * PH * PS * PDK];
__device__ __nv_bfloat16 g_vlo[(size_t)PB * PH * PS * PDK];

__device__ __nv_bfloat16 g_pa_hi[3][(size_t)GEMM_M * GEMM_K];
__device__ __nv_bfloat16 g_pa_lo[3][(size_t)GEMM_M * GEMM_K];
__device__ __nv_bfloat16 g_pb_hi[4][(size_t)GEMM_N * GEMM_K];
__device__ __nv_bfloat16 g_pb_lo[4][(size_t)GEMM_N * GEMM_K];
__device__ __nv_bfloat16 g_ahi[(size_t)GEMM_M * GEMM_K];
__device__ __nv_bfloat16 g_alo[(size_t)GEMM_M * GEMM_K];

// ---------------------------------------------------------------------------
// PTX helpers (base ISA only)
// ---------------------------------------------------------------------------
__device__ __forceinline__ uint32_t smem_u32(const void* p) {
    uint32_t a;
    asm("{ .reg .u64 t; cvta.to.shared.u64 t, %1; cvt.u32.u64 %0, t; }"
        : "=r"(a) : "l"(p));
    return a;
}

__device__ __forceinline__ void cp16(uint32_t saddr, const void* gaddr) {
    asm volatile("cp.async.cg.shared.global [%0], [%1], 16;"
                 :: "r"(saddr), "l"(gaddr) : "memory");
}
#define CP_COMMIT() asm volatile("cp.async.commit_group;" ::: "memory")
#define CP_WAIT1()  asm volatile("cp.async.wait_group 1;" ::: "memory")
#define CP_WAIT0()  asm volatile("cp.async.wait_group 0;" ::: "memory")

__device__ __forceinline__ void ldsm_x4(uint32_t& r0, uint32_t& r1,
                                        uint32_t& r2, uint32_t& r3,
                                        uint32_t addr) {
    asm volatile("ldmatrix.sync.aligned.m8n8.x4.shared.b16 {%0,%1,%2,%3}, [%4];"
                 : "=r"(r0), "=r"(r1), "=r"(r2), "=r"(r3) : "r"(addr));
}

__device__ __forceinline__ void ldsm_x4_t(uint32_t& r0, uint32_t& r1,
                                          uint32_t& r2, uint32_t& r3,
                                          uint32_t addr) {
    asm volatile("ldmatrix.sync.aligned.m8n8.x4.trans.shared.b16 {%0,%1,%2,%3}, [%4];"
                 : "=r"(r0), "=r"(r1), "=r"(r2), "=r"(r3) : "r"(addr));
}

__device__ __forceinline__ void mma_bf16(float* d, const uint32_t* a,
                                         const uint32_t* b) {
    asm volatile(
        "mma.sync.aligned.m16n8k16.row.col.f32.bf16.bf16.f32 "
        "{%0,%1,%2,%3}, {%4,%5,%6,%7}, {%8,%9}, {%0,%1,%2,%3};"
        : "+f"(d[0]), "+f"(d[1]), "+f"(d[2]), "+f"(d[3])
        : "r"(a[0]), "r"(a[1]), "r"(a[2]), "r"(a[3]),
          "r"(b[0]), "r"(b[1]));
}

// split (a, b) fp32 pair into packed bf16x2 hi + bf16x2 lo
__device__ __forceinline__ void split2(float a, float b,
                                       uint32_t& hi, uint32_t& lo) {
    __nv_bfloat16 ha = __float2bfloat16(a);
    __nv_bfloat16 hb = __float2bfloat16(b);
    hi = ((uint32_t)__bfloat16_as_ushort(hb) << 16) |
         (uint32_t)__bfloat16_as_ushort(ha);
    __nv_bfloat162 r = __floats2bfloat162_rn(a - __bfloat162float(ha),
                                             b - __bfloat162float(hb));
    lo = *reinterpret_cast<uint32_t*>(&r);
}

// ---------------------------------------------------------------------------
// Fused split kernel: z 0..2 = input planes (MLP-4 elementwise split),
// z 3..6 = weight planes (transpose + split). One launch instead of two
// serialized ones — the two HBM-bound phases co-schedule across SMs.
// ---------------------------------------------------------------------------
struct SplitAllParams {
    const float* a_src[3];
    __nv_bfloat16* a_hi[3];
    __nv_bfloat16* a_lo[3];
    const float* w_src[4];
    __nv_bfloat16* w_hi[4];
    __nv_bfloat16* w_lo[4];
};

__global__ __launch_bounds__(256) void split_all_kernel(SplitAllParams P)
{
    __shared__ float t[32][33];
    const int z = blockIdx.z;
    if (z < 3) {
        const float4* xp = (const float4*)P.a_src[z];
        uint32_t* hp = (uint32_t*)P.a_hi[z];
        uint32_t* lp = (uint32_t*)P.a_lo[z];
        const int base = blockIdx.x * 1024 + threadIdx.x;

        float4 v[4];
#pragma unroll
        for (int j = 0; j < 4; j++) v[j] = xp[base + j * 256];
#pragma unroll
        for (int j = 0; j < 4; j++) {
            int i = base + j * 256;
            uint32_t h0, l0, h1, l1;
            split2(v[j].x, v[j].y, h0, l0);
            split2(v[j].z, v[j].w, h1, l1);
            hp[2 * i + 0] = h0;
            hp[2 * i + 1] = h1;
            lp[2 * i + 0] = l0;
            lp[2 * i + 1] = l1;
        }
    } else {
        const float* W = P.w_src[z - 3];
        __nv_bfloat16* hi = P.w_hi[z - 3];
        __nv_bfloat16* lo = P.w_lo[z - 3];
        const int tx = threadIdx.x & 31;
        const int ty = threadIdx.x >> 5;         // 0..7
        const int n0 = (blockIdx.x & 31) * 32;
        const int k0 = (blockIdx.x >> 5) * 32;
#pragma unroll
        for (int i = 0; i < 32; i += 8)
            t[ty + i][tx] = W[(size_t)(k0 + ty + i) * GEMM_N + n0 + tx];
        __syncthreads();
#pragma unroll
        for (int i = 0; i < 32; i += 8) {
            float v = t[tx][ty + i];
            __nv_bfloat16 h = __float2bfloat16(v);
            size_t o = (size_t)(n0 + ty + i) * GEMM_K + k0 + tx;
            hi[o] = h;
            lo[o] = __float2bfloat16(v - __bfloat162float(h));
        }
    }
}

// ---------------------------------------------------------------------------
// HMMA GEMM core (measured-best Round 13): 128x128 block, BK=32, 8 warps
// (4M x 2N, warp tile 32x64), hi/lo 3-pass, 2-stage, 80KB smem -> 2 CTAs/SM,
// B fragments consumed in 4-column halves to cap live registers.
// ---------------------------------------------------------------------------
constexpr int GBK = 32;
constexpr int GSTR = 40;
constexpr int GTILE_B = 128 * GSTR * 2;         // 10240
constexpr int GSTAGE_B = 4 * GTILE_B;           // 40960
constexpr int GSM_TOTAL = 2 * GSTAGE_B;         // 81920
constexpr int GNCH = GEMM_K / GBK;              // 32

__device__ __forceinline__ void g_load_tile(
    uint32_t sdst, const __nv_bfloat16* __restrict__ g, int row0, int k0, int tid)
{
#pragma unroll
    for (int i = 0; i < 2; i++) {
        int s = tid + i * 256;
        int r = s >> 2;
        int c = s & 3;
        cp16(sdst + (uint32_t)(r * (GSTR * 2) + c * 16),
             g + (size_t)(row0 + r) * GEMM_K + k0 + c * 8);
    }
}

__device__ __forceinline__ void g_load_stage(
    uint32_t st, const __nv_bfloat16* Ahi, const __nv_bfloat16* Alo,
    const __nv_bfloat16* Bhi, const __nv_bfloat16* Blo,
    int bm, int bn, int k0, int tid)
{
    g_load_tile(st + 0 * GTILE_B, Ahi, bm, k0, tid);
    g_load_tile(st + 1 * GTILE_B, Alo, bm, k0, tid);
    g_load_tile(st + 2 * GTILE_B, Bhi, bn, k0, tid);
    g_load_tile(st + 3 * GTILE_B, Blo, bn, k0, tid);
    CP_COMMIT();
}

__device__ __forceinline__ void gemm_core(
    uint32_t sb, int tid,
    const __nv_bfloat16* __restrict__ Ahi, const __nv_bfloat16* __restrict__ Alo,
    const __nv_bfloat16* __restrict__ Bhi, const __nv_bfloat16* __restrict__ Blo,
    int bm, int bn, float acc[2][8][4])
{
    const int lane = tid & 31;
    const int wid = tid >> 5;
    const int wm = wid >> 1;
    const int wn = wid & 1;

    const int a_r = ((lane >> 3) & 1) * 8 + (lane & 7);
    const int a_c = (lane >> 4) * 8;
    const int b_r = (lane >> 4) * 8 + (lane & 7);
    const int b_c = ((lane >> 3) & 1) * 8;

    g_load_stage(sb, Ahi, Alo, Bhi, Blo, bm, bn, 0, tid);

    for (int c = 0; c < GNCH; c++) {
        if (c + 1 < GNCH) {
            g_load_stage(sb + ((c + 1) & 1) * GSTAGE_B, Ahi, Alo, Bhi, Blo,
                         bm, bn, (c + 1) * GBK, tid);
            CP_WAIT1();
        } else {
            CP_WAIT0();
        }
        __syncthreads();

        const uint32_t st = sb + (c & 1) * GSTAGE_B;
        const uint32_t sAhi = st + 0 * GTILE_B;
        const uint32_t sAlo = st + 1 * GTILE_B;
        const uint32_t sBhi = st + 2 * GTILE_B;
        const uint32_t sBlo = st + 3 * GTILE_B;

#pragma unroll
        for (int ks = 0; ks < 2; ks++) {
            const int kc = ks * 16;
            uint32_t ah[2][4], al[2][4];
#pragma unroll
            for (int ma = 0; ma < 2; ma++) {
                uint32_t off =
                    (uint32_t)((wm * 32 + ma * 16 + a_r) * (GSTR * 2) +
                               (kc + a_c) * 2);
                ldsm_x4(ah[ma][0], ah[ma][1], ah[ma][2], ah[ma][3], sAhi + off);
                ldsm_x4(al[ma][0], al[ma][1], al[ma][2], al[ma][3], sAlo + off);
            }
#pragma unroll
            for (int h2 = 0; h2 < 2; h2++) {
                uint32_t bh[4][2], bl[4][2];
#pragma unroll
                for (int pa = 0; pa < 2; pa++) {
                    uint32_t off =
                        (uint32_t)((wn * 64 + (h2 * 2 + pa) * 16 + b_r) *
                                       (GSTR * 2) +
                                   (kc + b_c) * 2);
                    ldsm_x4(bh[2 * pa][0], bh[2 * pa][1],
                            bh[2 * pa + 1][0], bh[2 * pa + 1][1], sBhi + off);
                    ldsm_x4(bl[2 * pa][0], bl[2 * pa][1],
                            bl[2 * pa + 1][0], bl[2 * pa + 1][1], sBlo + off);
                }
#pragma unroll
                for (int ma = 0; ma < 2; ma++)
#pragma unroll
                    for (int nb = 0; nb < 4; nb++) {
                        int na = h2 * 4 + nb;
                        mma_bf16(acc[ma][na], ah[ma], bh[nb]);
                        mma_bf16(acc[ma][na], ah[ma], bl[nb]);
                        mma_bf16(acc[ma][na], al[ma], bh[nb]);
                    }
            }
        }
        __syncthreads();
    }
}

struct ProjParams {
    const __nv_bfloat16* ah[3];
    const __nv_bfloat16* al[3];
    const __nv_bfloat16* bh[3];
    const __nv_bfloat16* bl[3];
    const float* bias[3];
    __nv_bfloat16* ch[3];
    __nv_bfloat16* cl[3];
    float scale[3];
};

__global__ __launch_bounds__(256, 2) void proj_gemm3_kernel(ProjParams P)
{
    extern __shared__ __align__(128) char smem[];
    const uint32_t sb = smem_u32(smem);
    const int tid = threadIdx.x;
    const int z = blockIdx.z;
    const int bm = blockIdx.y * 128;
    const int bn = blockIdx.x * 128;

    float acc[2][8][4];
#pragma unroll
    for (int i = 0; i < 2; i++)
#pragma unroll
        for (int j = 0; j < 8; j++)
#pragma unroll
            for (int r = 0; r < 4; r++) acc[i][j][r] = 0.f;

    gemm_core(sb, tid, P.ah[z], P.al[z], P.bh[z], P.bl[z], bm, bn, acc);

    const float* bias = P.bias[z];
    const float scl = P.scale[z];
    __nv_bfloat16* Chi = P.ch[z];
    __nv_bfloat16* Clo = P.cl[z];
    const int wid = tid >> 5;
    const int lane = tid & 31;
    const int wm = wid >> 1;
    const int wn = wid & 1;
    const int lr = lane >> 2;
    const int lc = (lane & 3) * 2;
#pragma unroll
    for (int ma = 0; ma < 2; ma++) {
#pragma unroll
        for (int half = 0; half < 2; half++) {
            int row = bm + wm * 32 + ma * 16 + half * 8 + lr;
            int b = row / PT;
            int t = row - b * PT;
#pragma unroll
            for (int na = 0; na < 8; na++) {
                int col = bn + wn * 64 + na * 8 + lc;
                float v0 = (acc[ma][na][half * 2 + 0] + bias[col + 0]) * scl;
                float v1 = (acc[ma][na][half * 2 + 1] + bias[col + 1]) * scl;
                int h = col >> 6;
                int dk = col & 63;
                size_t o = (((size_t)(b * PH + h) * PT) + t) * PDK + dk;
                uint32_t hp, lp;
                split2(v0, v1, hp, lp);
                *(uint32_t*)(Chi + o) = hp;
                *(uint32_t*)(Clo + o) = lp;
            }
        }
    }
}

__global__ __launch_bounds__(256, 2) void out_gemm_kernel(
    const __nv_bfloat16* __restrict__ Ahi, const __nv_bfloat16* __restrict__ Alo,
    const __nv_bfloat16* __restrict__ Bhi, const __nv_bfloat16* __restrict__ Blo,
    const float* __restrict__ bias, float* __restrict__ C)
{
    extern __shared__ __align__(128) char smem[];
    const uint32_t sb = smem_u32(smem);
    const int tid = threadIdx.x;
    const int bm = blockIdx.y * 128;
    const int bn = blockIdx.x * 128;

    float acc[2][8][4];
#pragma unroll
    for (int i = 0; i < 2; i++)
#pragma unroll
        for (int j = 0; j < 8; j++)
#pragma unroll
            for (int r = 0; r < 4; r++) acc[i][j][r] = 0.f;

    gemm_core(sb, tid, Ahi, Alo, Bhi, Blo, bm, bn, acc);

    const int wid = tid >> 5;
    const int lane = tid & 31;
    const int wm = wid >> 1;
    const int wn = wid & 1;
    const int lr = lane >> 2;
    const int lc = (lane & 3) * 2;
#pragma unroll
    for (int ma = 0; ma < 2; ma++) {
#pragma unroll
        for (int half = 0; half < 2; half++) {
            int row = bm + wm * 32 + ma * 16 + half * 8 + lr;
#pragma unroll
            for (int na = 0; na < 8; na++) {
                int col = bn + wn * 64 + na * 8 + lc;
                float v0 = acc[ma][na][half * 2 + 0] + bias[col + 0];
                float v1 = acc[ma][na][half * 2 + 1] + bias[col + 1];
                float2* dst = (float2*)(C + (size_t)row * GEMM_N + col);
                *dst = make_float2(v0, v1);
            }
        }
    }
}

// ---------------------------------------------------------------------------
// Flash attention on mma.sync, full hi/lo, max-free base-2 softmax.
// Measured-good Round-13 config (128 threads, 32-row warp tiles) — verbatim.
// ---------------------------------------------------------------------------
constexpr int ASTR = 72;
constexpr int QTILE_B = 128 * ASTR * 2;
constexpr int KTILE_B = 64 * ASTR * 2;
constexpr int AT_SMEM = 2 * QTILE_B + 2 * 4 * KTILE_B;  // 110592

__device__ __forceinline__ void at_load_kv(
    uint32_t base, const __nv_bfloat16* kh, const __nv_bfloat16* kl,
    const __nv_bfloat16* vh, const __nv_bfloat16* vl,
    size_t gbase, int tid)
{
#pragma unroll
    for (int i = 0; i < 4; i++) {
        int s = tid + i * 128;
        int r = s >> 3;
        int c = s & 7;
        uint32_t doff = (uint32_t)(r * (ASTR * 2) + c * 16);
        size_t goff = gbase + (size_t)r * PDK + c * 8;
        cp16(base + 0 * KTILE_B + doff, kh + goff);
        cp16(base + 1 * KTILE_B + doff, kl + goff);
        cp16(base + 2 * KTILE_B + doff, vh + goff);
        cp16(base + 3 * KTILE_B + doff, vl + goff);
    }
}

__global__ __launch_bounds__(128, 1) void attn_mma_kernel(
    const __nv_bfloat16* __restrict__ qhi, const __nv_bfloat16* __restrict__ qlo,
    const __nv_bfloat16* __restrict__ khi, const __nv_bfloat16* __restrict__ klo,
    const __nv_bfloat16* __restrict__ vhi, const __nv_bfloat16* __restrict__ vlo,
    __nv_bfloat16* __restrict__ ohi, __nv_bfloat16* __restrict__ olo)
{
    extern __shared__ __align__(128) char smem[];
    const uint32_t sb = smem_u32(smem);
    const int tid = threadIdx.x;
    const int w = tid >> 5;
    const int lane = tid & 31;
    const int t0 = blockIdx.x * 128;
    const int h = blockIdx.y;
    const int b = blockIdx.z;
    const size_t bh = (size_t)(b * PH + h);

    const int a_r = ((lane >> 3) & 1) * 8 + (lane & 7);
    const int a_c = (lane >> 4) * 8;
    const int b_r = (lane >> 4) * 8 + (lane & 7);
    const int b_c = ((lane >> 3) & 1) * 8;

    {
        const __nv_bfloat16* qhb = qhi + (bh * PT + t0) * PDK;
        const __nv_bfloat16* qlb = qlo + (bh * PT + t0) * PDK;
#pragma unroll
        for (int i = 0; i < 8; i++) {
            int s = tid + i * 128;
            int r = s >> 3;
            int c = s & 7;
            uint32_t doff = (uint32_t)(r * (ASTR * 2) + c * 16);
            cp16(sb + doff, qhb + (size_t)r * PDK + c * 8);
            cp16(sb + QTILE_B + doff, qlb + (size_t)r * PDK + c * 8);
        }
        at_load_kv(sb + 2 * QTILE_B, khi, klo, vhi, vlo, bh * PS * PDK, tid);
        CP_COMMIT();
    }

    float l[2][2];
    float oa[2][8][4];
#pragma unroll
    for (int i = 0; i < 2; i++)
#pragma unroll
        for (int j = 0; j < 2; j++) l[i][j] = 0.f;
#pragma unroll
    for (int i = 0; i < 2; i++)
#pragma unroll
        for (int j = 0; j < 8; j++)
#pragma unroll
            for (int r = 0; r < 4; r++) oa[i][j][r] = 0.f;

    const int NT = PS / 64;

    for (int it = 0; it < NT; it++) {
        const int stage = it & 1;
        if (it + 1 < NT) {
            at_load_kv(sb + 2 * QTILE_B + (stage ^ 1) * 4 * KTILE_B,
                       khi, klo, vhi, vlo,
                       (bh * PS + (size_t)(it + 1) * 64) * PDK, tid);
            CP_COMMIT();
            CP_WAIT1();
        } else {
            CP_WAIT0();
        }
        __syncthreads();

        const uint32_t kb = sb + 2 * QTILE_B + stage * 4 * KTILE_B;
        const uint32_t sKh = kb + 0 * KTILE_B;
        const uint32_t sKl = kb + 1 * KTILE_B;
        const uint32_t sVh = kb + 2 * KTILE_B;
        const uint32_t sVl = kb + 3 * KTILE_B;

        float sc[2][8][4];
#pragma unroll
        for (int i = 0; i < 2; i++)
#pragma unroll
            for (int j = 0; j < 8; j++)
#pragma unroll
                for (int r = 0; r < 4; r++) sc[i][j][r] = 0.f;

#pragma unroll
        for (int kk = 0; kk < 4; kk++) {
            const int kc = kk * 16;
            uint32_t qh[2][4], ql[2][4], kh[8][2], kl[8][2];
#pragma unroll
            for (int ma = 0; ma < 2; ma++) {
                uint32_t off = (uint32_t)((w * 32 + ma * 16 + a_r) * (ASTR * 2) +
                                          (kc + a_c) * 2);
                ldsm_x4(qh[ma][0], qh[ma][1], qh[ma][2], qh[ma][3], sb + off);
                ldsm_x4(ql[ma][0], ql[ma][1], ql[ma][2], ql[ma][3],
                        sb + QTILE_B + off);
            }
#pragma unroll
            for (int nb = 0; nb < 4; nb++) {
                uint32_t off = (uint32_t)((nb * 16 + b_r) * (ASTR * 2) +
                                          (kc + b_c) * 2);
                ldsm_x4(kh[2 * nb][0], kh[2 * nb][1],
                        kh[2 * nb + 1][0], kh[2 * nb + 1][1], sKh + off);
                ldsm_x4(kl[2 * nb][0], kl[2 * nb][1],
                        kl[2 * nb + 1][0], kl[2 * nb + 1][1], sKl + off);
            }
#pragma unroll
            for (int ma = 0; ma < 2; ma++)
#pragma unroll
                for (int na = 0; na < 8; na++) {
                    mma_bf16(sc[ma][na], qh[ma], kh[na]);
                    mma_bf16(sc[ma][na], qh[ma], kl[na]);
                    mma_bf16(sc[ma][na], ql[ma], kh[na]);
                }
        }

        // ---- max-free base-2 softmax (lane-partial l) ----
#pragma unroll
        for (int ma = 0; ma < 2; ma++) {
            float rs0 = 0.f, rs1 = 0.f;
#pragma unroll
            for (int na = 0; na < 8; na++) {
                float p0 = exp2f(sc[ma][na][0]);
                float p1 = exp2f(sc[ma][na][1]);
                float p2 = exp2f(sc[ma][na][2]);
                float p3 = exp2f(sc[ma][na][3]);
                sc[ma][na][0] = p0; sc[ma][na][1] = p1;
                sc[ma][na][2] = p2; sc[ma][na][3] = p3;
                rs0 += p0 + p1;
                rs1 += p2 + p3;
            }
            l[ma][0] += rs0;
            l[ma][1] += rs1;
        }

        // ---- O += P V ----
#pragma unroll
        for (int kk = 0; kk < 4; kk++) {
            uint32_t ph[2][4], pl[2][4];
#pragma unroll
            for (int ma = 0; ma < 2; ma++) {
                split2(sc[ma][2 * kk][0],     sc[ma][2 * kk][1],     ph[ma][0], pl[ma][0]);
                split2(sc[ma][2 * kk][2],     sc[ma][2 * kk][3],     ph[ma][1], pl[ma][1]);
                split2(sc[ma][2 * kk + 1][0], sc[ma][2 * kk + 1][1], ph[ma][2], pl[ma][2]);
                split2(sc[ma][2 * kk + 1][2], sc[ma][2 * kk + 1][3], ph[ma][3], pl[ma][3]);
            }
            uint32_t vh[8][2], vl[8][2];
#pragma unroll
            for (int db = 0; db < 4; db++) {
                uint32_t off = (uint32_t)((kk * 16 + a_r) * (ASTR * 2) +
                                          (db * 16 + a_c) * 2);
                ldsm_x4_t(vh[2 * db][0], vh[2 * db][1],
                          vh[2 * db + 1][0], vh[2 * db + 1][1], sVh + off);
                ldsm_x4_t(vl[2 * db][0], vl[2 * db][1],
                          vl[2 * db + 1][0], vl[2 * db + 1][1], sVl + off);
            }
#pragma unroll
            for (int ma = 0; ma < 2; ma++)
#pragma unroll
                for (int nb = 0; nb < 8; nb++) {
                    mma_bf16(oa[ma][nb], ph[ma], vh[nb]);
                    mma_bf16(oa[ma][nb], ph[ma], vl[nb]);
                    mma_bf16(oa[ma][nb], pl[ma], vh[nb]);
                }
        }
        __syncthreads();
    }

    // ---- epilogue ----
#pragma unroll
    for (int ma = 0; ma < 2; ma++) {
#pragma unroll
        for (int half = 0; half < 2; half++) {
            float lt = l[ma][half];
            lt += __shfl_xor_sync(0xFFFFFFFFu, lt, 1);
            lt += __shfl_xor_sync(0xFFFFFFFFu, lt, 2);
            float invl = 1.0f / lt;
            int t = t0 + w * 32 + ma * 16 + half * 8 + (lane >> 2);
            size_t base = ((size_t)(b * PT + t)) * PD + h * PDK;
#pragma unroll
            for (int nb = 0; nb < 8; nb++) {
                int col = nb * 8 + 2 * (lane & 3);
                float v0 = oa[ma][nb][half * 2 + 0] * invl;
                float v1 = oa[ma][nb][half * 2 + 1] * invl;
                uint32_t hp, lp;
                split2(v0, v1, hp, lp);
                *(uint32_t*)(ohi + base + col) = hp;
                *(uint32_t*)(olo + base + col) = lp;
            }
        }
    }
}

// ---------------------------------------------------------------------------
extern "C" void kernel_launch(void* const* d_in, const int* in_sizes, int n_in,
                              void* d_out, int out_size)
{
    const float* query = (const float*)d_in[0];
    const float* value = (const float*)d_in[1];
    const float* key   = (const float*)d_in[2];
    const float* Wq    = (const float*)d_in[3];
    const float* bq    = (const float*)d_in[4];
    const float* Wk    = (const float*)d_in[5];
    const float* bk    = (const float*)d_in[6];
    const float* Wv    = (const float*)d_in[7];
    const float* bv    = (const float*)d_in[8];
    const float* Wo    = (const float*)d_in[9];
    const float* bo    = (const float*)d_in[10];
    float* out = (float*)d_out;

    __nv_bfloat16 *qhi, *qlo, *khi, *klo, *vhi, *vlo, *ahi, *alo;
    __nv_bfloat16 *pah, *pal, *pbh, *pbl;
    cudaGetSymbolAddress((void**)&qhi, g_qhi);
    cudaGetSymbolAddress((void**)&qlo, g_qlo);
    cudaGetSymbolAddress((void**)&khi, g_khi);
    cudaGetSymbolAddress((void**)&klo, g_klo);
    cudaGetSymbolAddress((void**)&vhi, g_vhi);
    cudaGetSymbolAddress((void**)&vlo, g_vlo);
    cudaGetSymbolAddress((void**)&ahi, g_ahi);
    cudaGetSymbolAddress((void**)&alo, g_alo);
    cudaGetSymbolAddress((void**)&pah, g_pa_hi);
    cudaGetSymbolAddress((void**)&pal, g_pa_lo);
    cudaGetSymbolAddress((void**)&pbh, g_pb_hi);
    cudaGetSymbolAddress((void**)&pbl, g_pb_lo);

    const size_t PA = (size_t)GEMM_M * GEMM_K;
    const size_t PBW = (size_t)GEMM_N * GEMM_K;

    cudaFuncSetAttribute(proj_gemm3_kernel,
                         cudaFuncAttributeMaxDynamicSharedMemorySize, GSM_TOTAL);
    cudaFuncSetAttribute(out_gemm_kernel,
                         cudaFuncAttributeMaxDynamicSharedMemorySize, GSM_TOTAL);
    cudaFuncSetAttribute(attn_mma_kernel,
                         cudaFuncAttributeMaxDynamicSharedMemorySize, AT_SMEM);

    // Fused splits: z 0..2 inputs, z 3..6 weights (one launch)
    SplitAllParams SP;
    SP.a_src[0] = query; SP.a_src[1] = key; SP.a_src[2] = value;
    for (int z = 0; z < 3; z++) {
        SP.a_hi[z] = pah + z * PA;
        SP.a_lo[z] = pal + z * PA;
    }
    SP.w_src[0] = Wq; SP.w_src[1] = Wk; SP.w_src[2] = Wv; SP.w_src[3] = Wo;
    for (int z = 0; z < 4; z++) {
        SP.w_hi[z] = pbh + z * PBW;
        SP.w_lo[z] = pbl + z * PBW;
    }
    split_all_kernel<<<dim3(1024, 1, 7), 256>>>(SP);

    ProjParams PP;
    for (int z = 0; z < 3; z++) {
        PP.ah[z] = pah + z * PA;
        PP.al[z] = pal + z * PA;
        PP.bh[z] = pbh + z * PBW;
        PP.bl[z] = pbl + z * PBW;
    }
    PP.bias[0] = bq; PP.bias[1] = bk; PP.bias[2] = bv;
    PP.ch[0] = qhi; PP.cl[0] = qlo;
    PP.ch[1] = khi; PP.cl[1] = klo;
    PP.ch[2] = vhi; PP.cl[2] = vlo;
    PP.scale[0] = 0.125f * 1.4426950408889634f;  // 1/sqrt(DK) * log2(e)
    PP.scale[1] = 1.0f;
    PP.scale[2] = 1.0f;
    proj_gemm3_kernel<<<dim3(GEMM_N / 128, GEMM_M / 128, 3), 256, GSM_TOTAL>>>(PP);

    attn_mma_kernel<<<dim3(PT / 128, PH, PB), 128, AT_SMEM>>>(
        qhi, qlo, khi, klo, vhi, vlo, ahi, alo);

    out_gemm_kernel<<<dim3(GEMM_N / 128, GEMM_M / 128), 256, GSM_TOTAL>>>(
        ahi, alo, pbh + 3 * PBW, pbl + 3 * PBW, bo, out);
}

// round 17
// speedup vs baseline: 1.1134x; 1.0283x over previous
#include <cuda_runtime.h>
#include <cuda_bf16.h>
#include <math.h>
#include <stdint.h>

// Problem constants
constexpr int PB = 2;      // batch
constexpr int PT = 2048;   // query seq
constexpr int PS = 2048;   // key/value seq
constexpr int PD = 1024;   // model dim
constexpr int PH = 16;     // heads
constexpr int PDK = 64;    // head dim

constexpr int GEMM_M = PB * PT;  // 4096
constexpr int GEMM_N = PD;       // 1024
constexpr int GEMM_K = PD;       // 1024

// ---------------------------------------------------------------------------
// Scratch (device globals — no allocation allowed)
// ---------------------------------------------------------------------------
__device__ __nv_bfloat16 g_qhi[(size_t)PB * PH * PT * PDK];
__device__ __nv_bfloat16 g_qlo[(size_t)PB * PH * PT * PDK];
__device__ __nv_bfloat16 g_khi[(size_t)PB * PH * PS * PDK];
__device__ __nv_bfloat16 g_klo[(size_t)PB * PH * PS * PDK];
__device__ __nv_bfloat16 g_vhi[(size_t)PB * PH * PS * PDK];
__device__ __nv_bfloat16 g_vlo[(size_t)PB * PH * PS * PDK];

__device__ __nv_bfloat16 g_pa_hi[3][(size_t)GEMM_M * GEMM_K];
__device__ __nv_bfloat16 g_pa_lo[3][(size_t)GEMM_M * GEMM_K];
__device__ __nv_bfloat16 g_pb_hi[4][(size_t)GEMM_N * GEMM_K];
__device__ __nv_bfloat16 g_pb_lo[4][(size_t)GEMM_N * GEMM_K];
__device__ __nv_bfloat16 g_ahi[(size_t)GEMM_M * GEMM_K];
__device__ __nv_bfloat16 g_alo[(size_t)GEMM_M * GEMM_K];

// ---------------------------------------------------------------------------
// PTX helpers (base ISA only)
// ---------------------------------------------------------------------------
__device__ __forceinline__ uint32_t smem_u32(const void* p) {
    uint32_t a;
    asm("{ .reg .u64 t; cvta.to.shared.u64 t, %1; cvt.u32.u64 %0, t; }"
        : "=r"(a) : "l"(p));
    return a;
}

__device__ __forceinline__ void cp16(uint32_t saddr, const void* gaddr) {
    asm volatile("cp.async.cg.shared.global [%0], [%1], 16;"
                 :: "r"(saddr), "l"(gaddr) : "memory");
}
#define CP_COMMIT() asm volatile("cp.async.commit_group;" ::: "memory")
#define CP_WAIT0()  asm volatile("cp.async.wait_group 0;" ::: "memory")

__device__ __forceinline__ void ldsm_x4(uint32_t& r0, uint32_t& r1,
                                        uint32_t& r2, uint32_t& r3,
                                        uint32_t addr) {
    asm volatile("ldmatrix.sync.aligned.m8n8.x4.shared.b16 {%0,%1,%2,%3}, [%4];"
                 : "=r"(r0), "=r"(r1), "=r"(r2), "=r"(r3) : "r"(addr));
}

__device__ __forceinline__ void ldsm_x4_t(uint32_t& r0, uint32_t& r1,
                                          uint32_t& r2, uint32_t& r3,
                                          uint32_t addr) {
    asm volatile("ldmatrix.sync.aligned.m8n8.x4.trans.shared.b16 {%0,%1,%2,%3}, [%4];"
                 : "=r"(r0), "=r"(r1), "=r"(r2), "=r"(r3) : "r"(addr));
}

__device__ __forceinline__ void mma_bf16(float* d, const uint32_t* a,
                                         const uint32_t* b) {
    asm volatile(
        "mma.sync.aligned.m16n8k16.row.col.f32.bf16.bf16.f32 "
        "{%0,%1,%2,%3}, {%4,%5,%6,%7}, {%8,%9}, {%0,%1,%2,%3};"
        : "+f"(d[0]), "+f"(d[1]), "+f"(d[2]), "+f"(d[3])
        : "r"(a[0]), "r"(a[1]), "r"(a[2]), "r"(a[3]),
          "r"(b[0]), "r"(b[1]));
}

// split (a, b) fp32 pair into packed bf16x2 hi + bf16x2 lo
__device__ __forceinline__ void split2(float a, float b,
                                       uint32_t& hi, uint32_t& lo) {
    __nv_bfloat16 ha = __float2bfloat16(a);
    __nv_bfloat16 hb = __float2bfloat16(b);
    hi = ((uint32_t)__bfloat16_as_ushort(hb) << 16) |
         (uint32_t)__bfloat16_as_ushort(ha);
    __nv_bfloat162 r = __floats2bfloat162_rn(a - __bfloat162float(ha),
                                             b - __bfloat162float(hb));
    lo = *reinterpret_cast<uint32_t*>(&r);
}

// ---------------------------------------------------------------------------
// Fused split kernel: z 0..2 = input planes, z 3..6 = weight planes
// ---------------------------------------------------------------------------
struct SplitAllParams {
    const float* a_src[3];
    __nv_bfloat16* a_hi[3];
    __nv_bfloat16* a_lo[3];
    const float* w_src[4];
    __nv_bfloat16* w_hi[4];
    __nv_bfloat16* w_lo[4];
};

__global__ __launch_bounds__(256) void split_all_kernel(SplitAllParams P)
{
    __shared__ float t[32][33];
    const int z = blockIdx.z;
    if (z < 3) {
        const float4* xp = (const float4*)P.a_src[z];
        uint32_t* hp = (uint32_t*)P.a_hi[z];
        uint32_t* lp = (uint32_t*)P.a_lo[z];
        const int base = blockIdx.x * 1024 + threadIdx.x;

        float4 v[4];
#pragma unroll
        for (int j = 0; j < 4; j++) v[j] = xp[base + j * 256];
#pragma unroll
        for (int j = 0; j < 4; j++) {
            int i = base + j * 256;
            uint32_t h0, l0, h1, l1;
            split2(v[j].x, v[j].y, h0, l0);
            split2(v[j].z, v[j].w, h1, l1);
            hp[2 * i + 0] = h0;
            hp[2 * i + 1] = h1;
            lp[2 * i + 0] = l0;
            lp[2 * i + 1] = l1;
        }
    } else {
        const float* W = P.w_src[z - 3];
        __nv_bfloat16* hi = P.w_hi[z - 3];
        __nv_bfloat16* lo = P.w_lo[z - 3];
        const int tx = threadIdx.x & 31;
        const int ty = threadIdx.x >> 5;
        const int n0 = (blockIdx.x & 31) * 32;
        const int k0 = (blockIdx.x >> 5) * 32;
#pragma unroll
        for (int i = 0; i < 32; i += 8)
            t[ty + i][tx] = W[(size_t)(k0 + ty + i) * GEMM_N + n0 + tx];
        __syncthreads();
#pragma unroll
        for (int i = 0; i < 32; i += 8) {
            float v = t[tx][ty + i];
            __nv_bfloat16 h = __float2bfloat16(v);
            size_t o = (size_t)(n0 + ty + i) * GEMM_K + k0 + tx;
            hi[o] = h;
            lo[o] = __float2bfloat16(v - __bfloat162float(h));
        }
    }
}

// ---------------------------------------------------------------------------
// HMMA GEMM core: 128x128 block, BK=32, 8 warps, hi/lo 3-pass, 2-stage,
// 2 CTAs/SM. NEW: single barrier per chunk (WAIT -> sync -> load-next ->
// MMAs); the one sync covers both data visibility and buffer-reuse safety.
// ---------------------------------------------------------------------------
constexpr int GBK = 32;
constexpr int GSTR = 40;
constexpr int GTILE_B = 128 * GSTR * 2;         // 10240
constexpr int GSTAGE_B = 4 * GTILE_B;           // 40960
constexpr int GSM_TOTAL = 2 * GSTAGE_B;         // 81920
constexpr int GNCH = GEMM_K / GBK;              // 32

__device__ __forceinline__ void g_load_tile(
    uint32_t sdst, const __nv_bfloat16* __restrict__ g, int row0, int k0, int tid)
{
#pragma unroll
    for (int i = 0; i < 2; i++) {
        int s = tid + i * 256;
        int r = s >> 2;
        int c = s & 3;
        cp16(sdst + (uint32_t)(r * (GSTR * 2) + c * 16),
             g + (size_t)(row0 + r) * GEMM_K + k0 + c * 8);
    }
}

__device__ __forceinline__ void g_load_stage(
    uint32_t st, const __nv_bfloat16* Ahi, const __nv_bfloat16* Alo,
    const __nv_bfloat16* Bhi, const __nv_bfloat16* Blo,
    int bm, int bn, int k0, int tid)
{
    g_load_tile(st + 0 * GTILE_B, Ahi, bm, k0, tid);
    g_load_tile(st + 1 * GTILE_B, Alo, bm, k0, tid);
    g_load_tile(st + 2 * GTILE_B, Bhi, bn, k0, tid);
    g_load_tile(st + 3 * GTILE_B, Blo, bn, k0, tid);
    CP_COMMIT();
}

__device__ __forceinline__ void gemm_core(
    uint32_t sb, int tid,
    const __nv_bfloat16* __restrict__ Ahi, const __nv_bfloat16* __restrict__ Alo,
    const __nv_bfloat16* __restrict__ Bhi, const __nv_bfloat16* __restrict__ Blo,
    int bm, int bn, float acc[2][8][4])
{
    const int lane = tid & 31;
    const int wid = tid >> 5;
    const int wm = wid >> 1;
    const int wn = wid & 1;

    const int a_r = ((lane >> 3) & 1) * 8 + (lane & 7);
    const int a_c = (lane >> 4) * 8;
    const int b_r = (lane >> 4) * 8 + (lane & 7);
    const int b_c = ((lane >> 3) & 1) * 8;

    g_load_stage(sb, Ahi, Alo, Bhi, Blo, bm, bn, 0, tid);

    for (int c = 0; c < GNCH; c++) {
        CP_WAIT0();
        __syncthreads();
        if (c + 1 < GNCH) {
            // safe: buffer (c+1)&1 was last read in iteration c-1, which all
            // threads finished before the sync above
            g_load_stage(sb + ((c + 1) & 1) * GSTAGE_B, Ahi, Alo, Bhi, Blo,
                         bm, bn, (c + 1) * GBK, tid);
        }

        const uint32_t st = sb + (c & 1) * GSTAGE_B;
        const uint32_t sAhi = st + 0 * GTILE_B;
        const uint32_t sAlo = st + 1 * GTILE_B;
        const uint32_t sBhi = st + 2 * GTILE_B;
        const uint32_t sBlo = st + 3 * GTILE_B;

#pragma unroll
        for (int ks = 0; ks < 2; ks++) {
            const int kc = ks * 16;
            uint32_t ah[2][4], al[2][4];
#pragma unroll
            for (int ma = 0; ma < 2; ma++) {
                uint32_t off =
                    (uint32_t)((wm * 32 + ma * 16 + a_r) * (GSTR * 2) +
                               (kc + a_c) * 2);
                ldsm_x4(ah[ma][0], ah[ma][1], ah[ma][2], ah[ma][3], sAhi + off);
                ldsm_x4(al[ma][0], al[ma][1], al[ma][2], al[ma][3], sAlo + off);
            }
#pragma unroll
            for (int h2 = 0; h2 < 2; h2++) {
                uint32_t bh[4][2], bl[4][2];
#pragma unroll
                for (int pa = 0; pa < 2; pa++) {
                    uint32_t off =
                        (uint32_t)((wn * 64 + (h2 * 2 + pa) * 16 + b_r) *
                                       (GSTR * 2) +
                                   (kc + b_c) * 2);
                    ldsm_x4(bh[2 * pa][0], bh[2 * pa][1],
                            bh[2 * pa + 1][0], bh[2 * pa + 1][1], sBhi + off);
                    ldsm_x4(bl[2 * pa][0], bl[2 * pa][1],
                            bl[2 * pa + 1][0], bl[2 * pa + 1][1], sBlo + off);
                }
#pragma unroll
                for (int ma = 0; ma < 2; ma++)
#pragma unroll
                    for (int nb = 0; nb < 4; nb++) {
                        int na = h2 * 4 + nb;
                        mma_bf16(acc[ma][na], ah[ma], bh[nb]);
                        mma_bf16(acc[ma][na], ah[ma], bl[nb]);
                        mma_bf16(acc[ma][na], al[ma], bh[nb]);
                    }
            }
        }
        // no trailing sync: next iteration's sync guards buffer reuse
    }
}

struct ProjParams {
    const __nv_bfloat16* ah[3];
    const __nv_bfloat16* al[3];
    const __nv_bfloat16* bh[3];
    const __nv_bfloat16* bl[3];
    const float* bias[3];
    __nv_bfloat16* ch[3];
    __nv_bfloat16* cl[3];
    float scale[3];
};

__global__ __launch_bounds__(256, 2) void proj_gemm3_kernel(ProjParams P)
{
    extern __shared__ __align__(128) char smem[];
    const uint32_t sb = smem_u32(smem);
    const int tid = threadIdx.x;
    const int z = blockIdx.z;
    const int bm = blockIdx.y * 128;
    const int bn = blockIdx.x * 128;

    float acc[2][8][4];
#pragma unroll
    for (int i = 0; i < 2; i++)
#pragma unroll
        for (int j = 0; j < 8; j++)
#pragma unroll
            for (int r = 0; r < 4; r++) acc[i][j][r] = 0.f;

    gemm_core(sb, tid, P.ah[z], P.al[z], P.bh[z], P.bl[z], bm, bn, acc);

    const float* bias = P.bias[z];
    const float scl = P.scale[z];
    __nv_bfloat16* Chi = P.ch[z];
    __nv_bfloat16* Clo = P.cl[z];
    const int wid = tid >> 5;
    const int lane = tid & 31;
    const int wm = wid >> 1;
    const int wn = wid & 1;
    const int lr = lane >> 2;
    const int lc = (lane & 3) * 2;
#pragma unroll
    for (int ma = 0; ma < 2; ma++) {
#pragma unroll
        for (int half = 0; half < 2; half++) {
            int row = bm + wm * 32 + ma * 16 + half * 8 + lr;
            int b = row / PT;
            int t = row - b * PT;
#pragma unroll
            for (int na = 0; na < 8; na++) {
                int col = bn + wn * 64 + na * 8 + lc;
                float v0 = (acc[ma][na][half * 2 + 0] + bias[col + 0]) * scl;
                float v1 = (acc[ma][na][half * 2 + 1] + bias[col + 1]) * scl;
                int h = col >> 6;
                int dk = col & 63;
                size_t o = (((size_t)(b * PH + h) * PT) + t) * PDK + dk;
                uint32_t hp, lp;
                split2(v0, v1, hp, lp);
                *(uint32_t*)(Chi + o) = hp;
                *(uint32_t*)(Clo + o) = lp;
            }
        }
    }
}

__global__ __launch_bounds__(256, 2) void out_gemm_kernel(
    const __nv_bfloat16* __restrict__ Ahi, const __nv_bfloat16* __restrict__ Alo,
    const __nv_bfloat16* __restrict__ Bhi, const __nv_bfloat16* __restrict__ Blo,
    const float* __restrict__ bias, float* __restrict__ C)
{
    extern __shared__ __align__(128) char smem[];
    const uint32_t sb = smem_u32(smem);
    const int tid = threadIdx.x;
    const int bm = blockIdx.y * 128;
    const int bn = blockIdx.x * 128;

    float acc[2][8][4];
#pragma unroll
    for (int i = 0; i < 2; i++)
#pragma unroll
        for (int j = 0; j < 8; j++)
#pragma unroll
            for (int r = 0; r < 4; r++) acc[i][j][r] = 0.f;

    gemm_core(sb, tid, Ahi, Alo, Bhi, Blo, bm, bn, acc);

    const int wid = tid >> 5;
    const int lane = tid & 31;
    const int wm = wid >> 1;
    const int wn = wid & 1;
    const int lr = lane >> 2;
    const int lc = (lane & 3) * 2;
#pragma unroll
    for (int ma = 0; ma < 2; ma++) {
#pragma unroll
        for (int half = 0; half < 2; half++) {
            int row = bm + wm * 32 + ma * 16 + half * 8 + lr;
#pragma unroll
            for (int na = 0; na < 8; na++) {
                int col = bn + wn * 64 + na * 8 + lc;
                float v0 = acc[ma][na][half * 2 + 0] + bias[col + 0];
                float v1 = acc[ma][na][half * 2 + 1] + bias[col + 1];
                float2* dst = (float2*)(C + (size_t)row * GEMM_N + col);
                *dst = make_float2(v0, v1);
            }
        }
    }
}

// ---------------------------------------------------------------------------
// Flash attention on mma.sync, full hi/lo, max-free base-2 softmax.
// Round-13 measured-good tiling; NEW: single barrier per KV tile
// (WAIT -> sync -> load-next -> compute).
// ---------------------------------------------------------------------------
constexpr int ASTR = 72;
constexpr int QTILE_B = 128 * ASTR * 2;
constexpr int KTILE_B = 64 * ASTR * 2;
constexpr int AT_SMEM = 2 * QTILE_B + 2 * 4 * KTILE_B;  // 110592

__device__ __forceinline__ void at_load_kv(
    uint32_t base, const __nv_bfloat16* kh, const __nv_bfloat16* kl,
    const __nv_bfloat16* vh, const __nv_bfloat16* vl,
    size_t gbase, int tid)
{
#pragma unroll
    for (int i = 0; i < 4; i++) {
        int s = tid + i * 128;
        int r = s >> 3;
        int c = s & 7;
        uint32_t doff = (uint32_t)(r * (ASTR * 2) + c * 16);
        size_t goff = gbase + (size_t)r * PDK + c * 8;
        cp16(base + 0 * KTILE_B + doff, kh + goff);
        cp16(base + 1 * KTILE_B + doff, kl + goff);
        cp16(base + 2 * KTILE_B + doff, vh + goff);
        cp16(base + 3 * KTILE_B + doff, vl + goff);
    }
}

__global__ __launch_bounds__(128, 1) void attn_mma_kernel(
    const __nv_bfloat16* __restrict__ qhi, const __nv_bfloat16* __restrict__ qlo,
    const __nv_bfloat16* __restrict__ khi, const __nv_bfloat16* __restrict__ klo,
    const __nv_bfloat16* __restrict__ vhi, const __nv_bfloat16* __restrict__ vlo,
    __nv_bfloat16* __restrict__ ohi, __nv_bfloat16* __restrict__ olo)
{
    extern __shared__ __align__(128) char smem[];
    const uint32_t sb = smem_u32(smem);
    const int tid = threadIdx.x;
    const int w = tid >> 5;
    const int lane = tid & 31;
    const int t0 = blockIdx.x * 128;
    const int h = blockIdx.y;
    const int b = blockIdx.z;
    const size_t bh = (size_t)(b * PH + h);

    const int a_r = ((lane >> 3) & 1) * 8 + (lane & 7);
    const int a_c = (lane >> 4) * 8;
    const int b_r = (lane >> 4) * 8 + (lane & 7);
    const int b_c = ((lane >> 3) & 1) * 8;

    {
        const __nv_bfloat16* qhb = qhi + (bh * PT + t0) * PDK;
        const __nv_bfloat16* qlb = qlo + (bh * PT + t0) * PDK;
#pragma unroll
        for (int i = 0; i < 8; i++) {
            int s = tid + i * 128;
            int r = s >> 3;
            int c = s & 7;
            uint32_t doff = (uint32_t)(r * (ASTR * 2) + c * 16);
            cp16(sb + doff, qhb + (size_t)r * PDK + c * 8);
            cp16(sb + QTILE_B + doff, qlb + (size_t)r * PDK + c * 8);
        }
        at_load_kv(sb + 2 * QTILE_B, khi, klo, vhi, vlo, bh * PS * PDK, tid);
        CP_COMMIT();
    }

    float l[2][2];
    float oa[2][8][4];
#pragma unroll
    for (int i = 0; i < 2; i++)
#pragma unroll
        for (int j = 0; j < 2; j++) l[i][j] = 0.f;
#pragma unroll
    for (int i = 0; i < 2; i++)
#pragma unroll
        for (int j = 0; j < 8; j++)
#pragma unroll
            for (int r = 0; r < 4; r++) oa[i][j][r] = 0.f;

    const int NT = PS / 64;

    for (int it = 0; it < NT; it++) {
        const int stage = it & 1;
        CP_WAIT0();
        __syncthreads();
        if (it + 1 < NT) {
            at_load_kv(sb + 2 * QTILE_B + (stage ^ 1) * 4 * KTILE_B,
                       khi, klo, vhi, vlo,
                       (bh * PS + (size_t)(it + 1) * 64) * PDK, tid);
            CP_COMMIT();
        }

        const uint32_t kb = sb + 2 * QTILE_B + stage * 4 * KTILE_B;
        const uint32_t sKh = kb + 0 * KTILE_B;
        const uint32_t sKl = kb + 1 * KTILE_B;
        const uint32_t sVh = kb + 2 * KTILE_B;
        const uint32_t sVl = kb + 3 * KTILE_B;

        float sc[2][8][4];
#pragma unroll
        for (int i = 0; i < 2; i++)
#pragma unroll
            for (int j = 0; j < 8; j++)
#pragma unroll
                for (int r = 0; r < 4; r++) sc[i][j][r] = 0.f;

#pragma unroll
        for (int kk = 0; kk < 4; kk++) {
            const int kc = kk * 16;
            uint32_t qh[2][4], ql[2][4], kh[8][2], kl[8][2];
#pragma unroll
            for (int ma = 0; ma < 2; ma++) {
                uint32_t off = (uint32_t)((w * 32 + ma * 16 + a_r) * (ASTR * 2) +
                                          (kc + a_c) * 2);
                ldsm_x4(qh[ma][0], qh[ma][1], qh[ma][2], qh[ma][3], sb + off);
                ldsm_x4(ql[ma][0], ql[ma][1], ql[ma][2], ql[ma][3],
                        sb + QTILE_B + off);
            }
#pragma unroll
            for (int nb = 0; nb < 4; nb++) {
                uint32_t off = (uint32_t)((nb * 16 + b_r) * (ASTR * 2) +
                                          (kc + b_c) * 2);
                ldsm_x4(kh[2 * nb][0], kh[2 * nb][1],
                        kh[2 * nb + 1][0], kh[2 * nb + 1][1], sKh + off);
                ldsm_x4(kl[2 * nb][0], kl[2 * nb][1],
                        kl[2 * nb + 1][0], kl[2 * nb + 1][1], sKl + off);
            }
#pragma unroll
            for (int ma = 0; ma < 2; ma++)
#pragma unroll
                for (int na = 0; na < 8; na++) {
                    mma_bf16(sc[ma][na], qh[ma], kh[na]);
                    mma_bf16(sc[ma][na], qh[ma], kl[na]);
                    mma_bf16(sc[ma][na], ql[ma], kh[na]);
                }
        }

        // ---- max-free base-2 softmax (lane-partial l) ----
#pragma unroll
        for (int ma = 0; ma < 2; ma++) {
            float rs0 = 0.f, rs1 = 0.f;
#pragma unroll
            for (int na = 0; na < 8; na++) {
                float p0 = exp2f(sc[ma][na][0]);
                float p1 = exp2f(sc[ma][na][1]);
                float p2 = exp2f(sc[ma][na][2]);
                float p3 = exp2f(sc[ma][na][3]);
                sc[ma][na][0] = p0; sc[ma][na][1] = p1;
                sc[ma][na][2] = p2; sc[ma][na][3] = p3;
                rs0 += p0 + p1;
                rs1 += p2 + p3;
            }
            l[ma][0] += rs0;
            l[ma][1] += rs1;
        }

        // ---- O += P V ----
#pragma unroll
        for (int kk = 0; kk < 4; kk++) {
            uint32_t ph[2][4], pl[2][4];
#pragma unroll
            for (int ma = 0; ma < 2; ma++) {
                split2(sc[ma][2 * kk][0],     sc[ma][2 * kk][1],     ph[ma][0], pl[ma][0]);
                split2(sc[ma][2 * kk][2],     sc[ma][2 * kk][3],     ph[ma][1], pl[ma][1]);
                split2(sc[ma][2 * kk + 1][0], sc[ma][2 * kk + 1][1], ph[ma][2], pl[ma][2]);
                split2(sc[ma][2 * kk + 1][2], sc[ma][2 * kk + 1][3], ph[ma][3], pl[ma][3]);
            }
            uint32_t vh[8][2], vl[8][2];
#pragma unroll
            for (int db = 0; db < 4; db++) {
                uint32_t off = (uint32_t)((kk * 16 + a_r) * (ASTR * 2) +
                                          (db * 16 + a_c) * 2);
                ldsm_x4_t(vh[2 * db][0], vh[2 * db][1],
                          vh[2 * db + 1][0], vh[2 * db + 1][1], sVh + off);
                ldsm_x4_t(vl[2 * db][0], vl[2 * db][1],
                          vl[2 * db + 1][0], vl[2 * db + 1][1], sVl + off);
            }
#pragma unroll
            for (int ma = 0; ma < 2; ma++)
#pragma unroll
                for (int nb = 0; nb < 8; nb++) {
                    mma_bf16(oa[ma][nb], ph[ma], vh[nb]);
                    mma_bf16(oa[ma][nb], ph[ma], vl[nb]);
                    mma_bf16(oa[ma][nb], pl[ma], vh[nb]);
                }
        }
        // no trailing sync: next iteration's sync guards buffer reuse
    }

    // ---- epilogue ----
#pragma unroll
    for (int ma = 0; ma < 2; ma++) {
#pragma unroll
        for (int half = 0; half < 2; half++) {
            float lt = l[ma][half];
            lt += __shfl_xor_sync(0xFFFFFFFFu, lt, 1);
            lt += __shfl_xor_sync(0xFFFFFFFFu, lt, 2);
            float invl = 1.0f / lt;
            int t = t0 + w * 32 + ma * 16 + half * 8 + (lane >> 2);
            size_t base = ((size_t)(b * PT + t)) * PD + h * PDK;
#pragma unroll
            for (int nb = 0; nb < 8; nb++) {
                int col = nb * 8 + 2 * (lane & 3);
                float v0 = oa[ma][nb][half * 2 + 0] * invl;
                float v1 = oa[ma][nb][half * 2 + 1] * invl;
                uint32_t hp, lp;
                split2(v0, v1, hp, lp);
                *(uint32_t*)(ohi + base + col) = hp;
                *(uint32_t*)(olo + base + col) = lp;
            }
        }
    }
}

// ---------------------------------------------------------------------------
extern "C" void kernel_launch(void* const* d_in, const int* in_sizes, int n_in,
                              void* d_out, int out_size)
{
    const float* query = (const float*)d_in[0];
    const float* value = (const float*)d_in[1];
    const float* key   = (const float*)d_in[2];
    const float* Wq    = (const float*)d_in[3];
    const float* bq    = (const float*)d_in[4];
    const float* Wk    = (const float*)d_in[5];
    const float* bk    = (const float*)d_in[6];
    const float* Wv    = (const float*)d_in[7];
    const float* bv    = (const float*)d_in[8];
    const float* Wo    = (const float*)d_in[9];
    const float* bo    = (const float*)d_in[10];
    float* out = (float*)d_out;

    __nv_bfloat16 *qhi, *qlo, *khi, *klo, *vhi, *vlo, *ahi, *alo;
    __nv_bfloat16 *pah, *pal, *pbh, *pbl;
    cudaGetSymbolAddress((void**)&qhi, g_qhi);
    cudaGetSymbolAddress((void**)&qlo, g_qlo);
    cudaGetSymbolAddress((void**)&khi, g_khi);
    cudaGetSymbolAddress((void**)&klo, g_klo);
    cudaGetSymbolAddress((void**)&vhi, g_vhi);
    cudaGetSymbolAddress((void**)&vlo, g_vlo);
    cudaGetSymbolAddress((void**)&ahi, g_ahi);
    cudaGetSymbolAddress((void**)&alo, g_alo);
    cudaGetSymbolAddress((void**)&pah, g_pa_hi);
    cudaGetSymbolAddress((void**)&pal, g_pa_lo);
    cudaGetSymbolAddress((void**)&pbh, g_pb_hi);
    cudaGetSymbolAddress((void**)&pbl, g_pb_lo);

    const size_t PA = (size_t)GEMM_M * GEMM_K;
    const size_t PBW = (size_t)GEMM_N * GEMM_K;

    cudaFuncSetAttribute(proj_gemm3_kernel,
                         cudaFuncAttributeMaxDynamicSharedMemorySize, GSM_TOTAL);
    cudaFuncSetAttribute(out_gemm_kernel,
                         cudaFuncAttributeMaxDynamicSharedMemorySize, GSM_TOTAL);
    cudaFuncSetAttribute(attn_mma_kernel,
                         cudaFuncAttributeMaxDynamicSharedMemorySize, AT_SMEM);

    SplitAllParams SP;
    SP.a_src[0] = query; SP.a_src[1] = key; SP.a_src[2] = value;
    for (int z = 0; z < 3; z++) {
        SP.a_hi[z] = pah + z * PA;
        SP.a_lo[z] = pal + z * PA;
    }
    SP.w_src[0] = Wq; SP.w_src[1] = Wk; SP.w_src[2] = Wv; SP.w_src[3] = Wo;
    for (int z = 0; z < 4; z++) {
        SP.w_hi[z] = pbh + z * PBW;
        SP.w_lo[z] = pbl + z * PBW;
    }
    split_all_kernel<<<dim3(1024, 1, 7), 256>>>(SP);

    ProjParams PP;
    for (int z = 0; z < 3; z++) {
        PP.ah[z] = pah + z * PA;
        PP.al[z] = pal + z * PA;
        PP.bh[z] = pbh + z * PBW;
        PP.bl[z] = pbl + z * PBW;
    }
    PP.bias[0] = bq; PP.bias[1] = bk; PP.bias[2] = bv;
    PP.ch[0] = qhi; PP.cl[0] = qlo;
    PP.ch[1] = khi; PP.cl[1] = klo;
    PP.ch[2] = vhi; PP.cl[2] = vlo;
    PP.scale[0] = 0.125f * 1.4426950408889634f;  // 1/sqrt(DK) * log2(e)
    PP.scale[1] = 1.0f;
    PP.scale[2] = 1.0f;
    proj_gemm3_kernel<<<dim3(GEMM_N / 128, GEMM_M / 128, 3), 256, GSM_TOTAL>>>(PP);

    attn_mma_kernel<<<dim3(PT / 128, PH, PB), 128, AT_SMEM>>>(
        qhi, qlo, khi, klo, vhi, vlo, ahi, alo);

    out_gemm_kernel<<<dim3(GEMM_N / 128, GEMM_M / 128), 256, GSM_TOTAL>>>(
        ahi, alo, pbh + 3 * PBW, pbl + 3 * PBW, bo, out);
}